// round 1
// baseline (speedup 1.0000x reference)
#include <cuda_runtime.h>
#include <math.h>
#include <math_constants.h>

// Problem constants
#define B_    2
#define L_    2048
#define D_    2048
#define H_    16
#define KVH_  4
#define HD_   128
#define GROUP_ 4
#define EPS_  1e-6f

// ---------------------------------------------------------------------------
// Scratch (allocation-free rule: __device__ globals)
// ---------------------------------------------------------------------------
__device__ float g_q [B_*L_*D_];          // 33.5 MB  q projection (then normed+roped in place)
__device__ float g_k [B_*L_*KVH_*HD_];    // 8.4 MB
__device__ float g_v [B_*L_*KVH_*HD_];    // 8.4 MB
__device__ float g_ao[B_*L_*D_];          // 33.5 MB  attention output (B,L,H*128)

// ---------------------------------------------------------------------------
// SGEMM: C[M,N] = A[M,K] * B[N,K]^T     (all dims multiples of 128, K mult of 8)
// 128x128 tile, BK=8, 256 threads, 8x8 micro-tile, register prefetch.
// ---------------------------------------------------------------------------
#define GBM 128
#define GBN 128
#define GBK 8

__global__ void sgemm_abt(const float* __restrict__ A,
                          const float* __restrict__ B,
                          float* __restrict__ C,
                          int M, int N, int K) {
    __shared__ float As[GBK][GBM];
    __shared__ float Bs[GBK][GBN];

    const int tid = threadIdx.x;          // 0..255
    const int tx  = tid & 15;
    const int ty  = tid >> 4;
    const int bm  = blockIdx.y * GBM;
    const int bn  = blockIdx.x * GBN;

    // tile load mapping: 1024 floats per operand = 256 threads x float4
    const int lr = tid >> 1;              // row within tile 0..127
    const int lk = (tid & 1) * 4;         // k offset 0 or 4

    const float* Aptr = A + (size_t)(bm + lr) * K + lk;
    const float* Bptr = B + (size_t)(bn + lr) * K + lk;

    float acc[8][8];
#pragma unroll
    for (int i = 0; i < 8; i++)
#pragma unroll
        for (int j = 0; j < 8; j++) acc[i][j] = 0.f;

    float4 av = *reinterpret_cast<const float4*>(Aptr);
    float4 bv = *reinterpret_cast<const float4*>(Bptr);

    for (int k0 = 0; k0 < K; k0 += GBK) {
        As[lk+0][lr] = av.x; As[lk+1][lr] = av.y;
        As[lk+2][lr] = av.z; As[lk+3][lr] = av.w;
        Bs[lk+0][lr] = bv.x; Bs[lk+1][lr] = bv.y;
        Bs[lk+2][lr] = bv.z; Bs[lk+3][lr] = bv.w;
        __syncthreads();

        if (k0 + GBK < K) {   // prefetch next tile while computing
            av = *reinterpret_cast<const float4*>(Aptr + k0 + GBK);
            bv = *reinterpret_cast<const float4*>(Bptr + k0 + GBK);
        }

#pragma unroll
        for (int kk = 0; kk < GBK; kk++) {
            float a[8], b[8];
#pragma unroll
            for (int i = 0; i < 8; i++) a[i] = As[kk][ty + 16*i];
#pragma unroll
            for (int j = 0; j < 8; j++) b[j] = Bs[kk][tx + 16*j];
#pragma unroll
            for (int i = 0; i < 8; i++)
#pragma unroll
                for (int j = 0; j < 8; j++) acc[i][j] += a[i] * b[j];
        }
        __syncthreads();
    }

#pragma unroll
    for (int i = 0; i < 8; i++) {
        const size_t r = (size_t)(bm + ty + 16*i);
#pragma unroll
        for (int j = 0; j < 8; j++)
            C[r * N + bn + tx + 16*j] = acc[i][j];
    }
}

// ---------------------------------------------------------------------------
// RMSNorm (per head vector of 128) + RoPE, in place. One warp per (b,l,h).
// ---------------------------------------------------------------------------
__global__ void rms_rope_kernel(float* __restrict__ X,
                                const float* __restrict__ gamma,
                                int heads) {
    const int warp = (blockIdx.x * blockDim.x + threadIdx.x) >> 5;
    const int lane = threadIdx.x & 31;
    const int h = warp % heads;
    const int l = (warp / heads) % L_;
    const int b = warp / (heads * L_);

    float* vec = X + ((size_t)(b * L_ + l) * heads + h) * HD_;

    // lane owns pairs p0 = lane, p1 = lane + 32
    const int p0 = lane, p1 = lane + 32;
    float x0a = vec[2*p0],   x1a = vec[2*p0+1];
    float x0b = vec[2*p1],   x1b = vec[2*p1+1];

    float ss = x0a*x0a + x1a*x1a + x0b*x0b + x1b*x1b;
#pragma unroll
    for (int off = 16; off; off >>= 1)
        ss += __shfl_xor_sync(0xffffffffu, ss, off);

    const float inv = rsqrtf(ss * (1.0f / HD_) + EPS_);
    const float LOG2_THETA = 13.287712379549449f;   // log2(10000)
    const float fl = (float)l;

    {
        float g0 = gamma[2*p0], g1 = gamma[2*p0+1];
        float re = x0a * inv * g0, im = x1a * inv * g1;
        float fr = fl * exp2f(-(2.0f * p0 / (float)HD_) * LOG2_THETA);
        float s, c; sincosf(fr, &s, &c);
        vec[2*p0]   = re * c - im * s;
        vec[2*p0+1] = re * s + im * c;
    }
    {
        float g0 = gamma[2*p1], g1 = gamma[2*p1+1];
        float re = x0b * inv * g0, im = x1b * inv * g1;
        float fr = fl * exp2f(-(2.0f * p1 / (float)HD_) * LOG2_THETA);
        float s, c; sincosf(fr, &s, &c);
        vec[2*p1]   = re * c - im * s;
        vec[2*p1+1] = re * s + im * c;
    }
}

// ---------------------------------------------------------------------------
// Flash attention (fp32, online softmax). Block = (qtile=64, head, batch).
// Q/K/V tiles in smem (stride 132 -> float4 aligned, conflict-free),
// S/P tile in smem (stride 68), O accumulator in registers (4x8 per thread).
// ---------------------------------------------------------------------------
#define ATM 64
#define ATN 64
#define QSTR 132
#define SSTR 68

// smem floats: 3*64*132 (Q,K,V) + 64*68 (S) + 3*64 (m,l,alpha) ; + 64 ints mask
#define FA_SMEM_BYTES ((3*64*QSTR + 64*SSTR + 3*64) * 4 + 64 * 4)

__global__ __launch_bounds__(256, 1)
void flash_attn_kernel(const float* __restrict__ Qg,
                       const float* __restrict__ Kg,
                       const float* __restrict__ Vg,
                       const int*   __restrict__ maskg,
                       float* __restrict__ Og) {
    extern __shared__ float sm[];
    float* Qs  = sm;                      // [64][132]
    float* Ks  = Qs + 64 * QSTR;          // [64][132]
    float* Vs  = Ks + 64 * QSTR;          // [64][132]
    float* Ss  = Vs + 64 * QSTR;          // [64][68]
    float* m_s = Ss + 64 * SSTR;          // [64]
    float* l_s = m_s + 64;                // [64]
    float* al_s= l_s + 64;                // [64]
    int*   msk = (int*)(al_s + 64);       // [64]

    const int tid = threadIdx.x;
    const int tx  = tid & 15;
    const int ty  = tid >> 4;
    const int qt  = blockIdx.x;
    const int h   = blockIdx.y;
    const int b   = blockIdx.z;
    const int kvh = h / GROUP_;
    const int q0  = qt * ATM;

    // load Q tile (64 rows x 128) as float4
    for (int r = tid; r < 64 * 32; r += 256) {
        const int row = r >> 5;
        const int c4  = (r & 31) * 4;
        float4 v = *reinterpret_cast<const float4*>(
            Qg + (size_t)(b * L_ + q0 + row) * D_ + h * HD_ + c4);
        *reinterpret_cast<float4*>(&Qs[row * QSTR + c4]) = v;
    }
    if (tid < 64) { m_s[tid] = -CUDART_INF_F; l_s[tid] = 0.f; }

    float o[4][8];
#pragma unroll
    for (int i = 0; i < 4; i++)
#pragma unroll
        for (int j = 0; j < 8; j++) o[i][j] = 0.f;

    const float scale = 0.08838834764831845f;  // 1/sqrt(128)

    for (int kt = 0; kt < L_ / ATN; kt++) {
        const int j0 = kt * ATN;
        __syncthreads();   // protect K/V/S reuse from previous iteration

        for (int r = tid; r < 64 * 32; r += 256) {
            const int row = r >> 5;
            const int c4  = (r & 31) * 4;
            const size_t gidx = (size_t)(b * L_ + j0 + row) * (KVH_ * HD_)
                              + kvh * HD_ + c4;
            *reinterpret_cast<float4*>(&Ks[row * QSTR + c4]) =
                *reinterpret_cast<const float4*>(Kg + gidx);
            *reinterpret_cast<float4*>(&Vs[row * QSTR + c4]) =
                *reinterpret_cast<const float4*>(Vg + gidx);
        }
        if (tid < 64) msk[tid] = maskg[b * L_ + j0 + tid];
        __syncthreads();

        // ---- S = Q K^T (64x64x128), 4x4 micro-tile, float4 LDS ----
        float s[4][4];
#pragma unroll
        for (int i = 0; i < 4; i++)
#pragma unroll
            for (int j = 0; j < 4; j++) s[i][j] = 0.f;

        for (int d0 = 0; d0 < HD_; d0 += 4) {
            float4 a4[4], b4[4];
#pragma unroll
            for (int ii = 0; ii < 4; ii++)
                a4[ii] = *reinterpret_cast<const float4*>(&Qs[(ty + 16*ii) * QSTR + d0]);
#pragma unroll
            for (int jj = 0; jj < 4; jj++)
                b4[jj] = *reinterpret_cast<const float4*>(&Ks[(tx + 16*jj) * QSTR + d0]);
#pragma unroll
            for (int ii = 0; ii < 4; ii++)
#pragma unroll
                for (int jj = 0; jj < 4; jj++)
                    s[ii][jj] += a4[ii].x * b4[jj].x + a4[ii].y * b4[jj].y
                               + a4[ii].z * b4[jj].z + a4[ii].w * b4[jj].w;
        }
#pragma unroll
        for (int ii = 0; ii < 4; ii++)
#pragma unroll
            for (int jj = 0; jj < 4; jj++)
                Ss[(ty + 16*ii) * SSTR + tx + 16*jj] = s[ii][jj] * scale;
        __syncthreads();

        // ---- online softmax row pass (one thread per row) ----
        if (tid < 64) {
            float m_old = m_s[tid];
            float m_new = m_old;
            float* row = &Ss[tid * SSTR];
#pragma unroll 8
            for (int j = 0; j < ATN; j++)
                if (msk[j]) m_new = fmaxf(m_new, row[j]);
            float alpha, rsum = 0.f;
            if (m_new == -CUDART_INF_F) {
                alpha = 1.f;
                for (int j = 0; j < ATN; j++) row[j] = 0.f;
            } else {
                alpha = __expf(m_old - m_new);
#pragma unroll 8
                for (int j = 0; j < ATN; j++) {
                    float p = msk[j] ? __expf(row[j] - m_new) : 0.f;
                    row[j] = p;
                    rsum += p;
                }
            }
            l_s[tid]  = l_s[tid] * alpha + rsum;
            m_s[tid]  = m_new;
            al_s[tid] = alpha;
        }
        __syncthreads();

        // ---- O = O*alpha + P V  (64 x 128 x 64), thread tile 4(i) x 8(d) ----
        float al[4];
#pragma unroll
        for (int ii = 0; ii < 4; ii++) al[ii] = al_s[ty + 16*ii];
#pragma unroll
        for (int ii = 0; ii < 4; ii++)
#pragma unroll
            for (int dd = 0; dd < 8; dd++) o[ii][dd] *= al[ii];

        for (int jb = 0; jb < ATN; jb += 4) {
            float a_[4][4];
#pragma unroll
            for (int ii = 0; ii < 4; ii++)
                *reinterpret_cast<float4*>(a_[ii]) =
                    *reinterpret_cast<const float4*>(&Ss[(ty + 16*ii) * SSTR + jb]);
#pragma unroll
            for (int u = 0; u < 4; u++) {
                const int j = jb + u;
                float4 v0 = *reinterpret_cast<const float4*>(&Vs[j * QSTR + tx * 8]);
                float4 v1 = *reinterpret_cast<const float4*>(&Vs[j * QSTR + tx * 8 + 4]);
#pragma unroll
                for (int ii = 0; ii < 4; ii++) {
                    const float p = a_[ii][u];
                    o[ii][0] += p * v0.x; o[ii][1] += p * v0.y;
                    o[ii][2] += p * v0.z; o[ii][3] += p * v0.w;
                    o[ii][4] += p * v1.x; o[ii][5] += p * v1.y;
                    o[ii][6] += p * v1.z; o[ii][7] += p * v1.w;
                }
            }
        }
    }

    // epilogue: normalize and store (values in l_s stable: sync before last PV)
#pragma unroll
    for (int ii = 0; ii < 4; ii++) {
        const float lv  = l_s[ty + 16*ii];
        const float inv = lv > 0.f ? 1.f / lv : 0.f;
        const size_t base = (size_t)(b * L_ + q0 + ty + 16*ii) * D_
                          + h * HD_ + tx * 8;
        float4 r0 = make_float4(o[ii][0]*inv, o[ii][1]*inv, o[ii][2]*inv, o[ii][3]*inv);
        float4 r1 = make_float4(o[ii][4]*inv, o[ii][5]*inv, o[ii][6]*inv, o[ii][7]*inv);
        *reinterpret_cast<float4*>(Og + base)     = r0;
        *reinterpret_cast<float4*>(Og + base + 4) = r1;
    }
}

// ---------------------------------------------------------------------------
// Launch
// ---------------------------------------------------------------------------
extern "C" void kernel_launch(void* const* d_in, const int* in_sizes, int n_in,
                              void* d_out, int out_size) {
    const float* x    = (const float*)d_in[0];
    const int*   mask = (const int*)  d_in[1];
    const float* Wq   = (const float*)d_in[2];
    const float* Wk   = (const float*)d_in[3];
    const float* Wv   = (const float*)d_in[4];
    const float* Wo   = (const float*)d_in[5];
    const float* qg   = (const float*)d_in[6];
    const float* kg   = (const float*)d_in[7];
    float* out = (float*)d_out;

    float *q, *k, *v, *ao;
    cudaGetSymbolAddress((void**)&q,  g_q);
    cudaGetSymbolAddress((void**)&k,  g_k);
    cudaGetSymbolAddress((void**)&v,  g_v);
    cudaGetSymbolAddress((void**)&ao, g_ao);

    cudaFuncSetAttribute(flash_attn_kernel,
                         cudaFuncAttributeMaxDynamicSharedMemorySize,
                         FA_SMEM_BYTES);

    const int M = B_ * L_;   // 4096
    dim3 blk(256);

    // projections
    sgemm_abt<<<dim3(D_ / GBN,            M / GBM), blk>>>(x, Wq, q, M, D_,          D_);
    sgemm_abt<<<dim3((KVH_*HD_) / GBN,    M / GBM), blk>>>(x, Wk, k, M, KVH_ * HD_,  D_);
    sgemm_abt<<<dim3((KVH_*HD_) / GBN,    M / GBM), blk>>>(x, Wv, v, M, KVH_ * HD_,  D_);

    // rmsnorm + rope (in place), one warp per head vector
    rms_rope_kernel<<<(B_ * L_ * H_)   / 8, 256>>>(q, qg, H_);
    rms_rope_kernel<<<(B_ * L_ * KVH_) / 8, 256>>>(k, kg, KVH_);

    // fused attention
    flash_attn_kernel<<<dim3(L_ / ATM, H_, B_), 256, FA_SMEM_BYTES>>>(q, k, v, mask, ao);

    // output projection
    sgemm_abt<<<dim3(D_ / GBN, M / GBM), blk>>>(ao, Wo, out, M, D_, D_);
}

// round 2
// speedup vs baseline: 3.2839x; 3.2839x over previous
#include <cuda_runtime.h>
#include <cuda_bf16.h>
#include <math.h>
#include <math_constants.h>
#include <stdint.h>

#define B_    2
#define L_    2048
#define D_    2048
#define H_    16
#define KVH_  4
#define HD_   128
#define EPS_  1e-6f

typedef __nv_bfloat16 bf16;

// ---------------------------------------------------------------------------
// Static scratch (allocation-free rule)
// ---------------------------------------------------------------------------
__device__ float g_q [B_*L_*D_];                 // fp32 q (rms+rope in place)
__device__ float g_k [B_*L_*KVH_*HD_];
__device__ float g_v [B_*L_*KVH_*HD_];
__device__ float g_ao[B_*L_*D_];
__device__ float g_S [B_*H_*L_*L_];              // 536 MB scores

// bf16 split planes
__device__ bf16 g_xh [B_*L_*D_],      g_xl [B_*L_*D_];
__device__ bf16 g_wqh[D_*D_],         g_wql[D_*D_];
__device__ bf16 g_wkh[KVH_*HD_*D_],   g_wkl[KVH_*HD_*D_];
__device__ bf16 g_wvh[KVH_*HD_*D_],   g_wvl[KVH_*HD_*D_];
__device__ bf16 g_woh[D_*D_],         g_wol[D_*D_];
__device__ bf16 g_qh [B_*L_*D_],      g_ql [B_*L_*D_];
__device__ bf16 g_kh [B_*L_*KVH_*HD_],g_kl [B_*L_*KVH_*HD_];
__device__ bf16 g_vh [B_*L_*KVH_*HD_],g_vl [B_*L_*KVH_*HD_];
__device__ bf16 g_Ph [B_*H_*L_*L_],   g_Pl [B_*H_*L_*L_];   // 268 MB each
__device__ bf16 g_aoh[B_*L_*D_],      g_aol[B_*L_*D_];

// ---------------------------------------------------------------------------
// PTX helpers
// ---------------------------------------------------------------------------
__device__ __forceinline__ void mma_bf16(float* c, const uint32_t* a, const uint32_t* b) {
    asm volatile(
        "mma.sync.aligned.m16n8k16.row.col.f32.bf16.bf16.f32 "
        "{%0,%1,%2,%3}, {%4,%5,%6,%7}, {%8,%9}, {%0,%1,%2,%3};\n"
        : "+f"(c[0]), "+f"(c[1]), "+f"(c[2]), "+f"(c[3])
        : "r"(a[0]), "r"(a[1]), "r"(a[2]), "r"(a[3]), "r"(b[0]), "r"(b[1]));
}

__device__ __forceinline__ void cp16(const bf16* dst_s, const bf16* src_g) {
    uint32_t d = (uint32_t)__cvta_generic_to_shared(dst_s);
    asm volatile("cp.async.cg.shared.global [%0], [%1], 16;\n"
                 :: "r"(d), "l"(src_g) : "memory");
}
__device__ __forceinline__ void cp_commit() {
    asm volatile("cp.async.commit_group;\n" ::: "memory");
}
template<int N>
__device__ __forceinline__ void cp_wait() {
    asm volatile("cp.async.wait_group %0;\n" :: "n"(N) : "memory");
}

__device__ __forceinline__ uint32_t pack_bf16(bf16 lo, bf16 hi) {
    uint32_t a = *reinterpret_cast<unsigned short*>(&lo);
    uint32_t b = *reinterpret_cast<unsigned short*>(&hi);
    return a | (b << 16);
}

// ---------------------------------------------------------------------------
// GEMM core: C[M,N] fp32 = (Ah+Al)[M,K] * (Bh+Bl)   (3-product bf16 split)
// TB=true : B stored [N,K] (row-major, K contiguous)  -> C = A * B^T
// TB=false: B stored [K,N] (row-major, N contiguous)  -> C = A * B
// 128x128 tile, BK=32, 256 threads (8 warps = 2x4), double-buffered cp.async.
// ---------------------------------------------------------------------------
#define BM 128
#define BN 128
#define BK 32
#define APAD 40      // halves per smem row (conflict-free: 20g+t distinct banks)
#define BKPAD 136    // halves per smem row for k-major B (128 + 8)

#define SM_A_HALVES (2*2*BM*APAD)        // 20480
#define SM_BTB_HALVES (2*2*BN*APAD)      // 20480
#define SM_BKM_HALVES (2*2*BK*BKPAD)     // 17408
#define SMEM_TB_BYTES ((SM_A_HALVES + SM_BTB_HALVES)*2)   // 81920
#define SMEM_KM_BYTES ((SM_A_HALVES + SM_BKM_HALVES)*2)   // 75776

template<bool TB>
__device__ __forceinline__ void gemm_core(
    const bf16* __restrict__ Ah, const bf16* __restrict__ Al, int lda,
    const bf16* __restrict__ Bh, const bf16* __restrict__ Bl, int ldb,
    float* __restrict__ C, int ldc, int K)
{
    extern __shared__ bf16 sh[];
    bf16* sA = sh;
    bf16* sB = sh + SM_A_HALVES;

    const int tid = threadIdx.x;
    const int m0 = blockIdx.y * BM;
    const int n0 = blockIdx.x * BN;

    const bf16* Ap[2] = { Ah + (size_t)m0 * lda, Al + (size_t)m0 * lda };
    const bf16* Bp[2];
    if (TB) { Bp[0] = Bh + (size_t)n0 * ldb; Bp[1] = Bl + (size_t)n0 * ldb; }
    else    { Bp[0] = Bh + n0;               Bp[1] = Bl + n0; }

    const int lane = tid & 31;
    const int g    = lane >> 2;
    const int t    = lane & 3;
    const int warp = tid >> 5;
    const int wm   = warp >> 2;   // 0..1
    const int wn   = warp & 3;    // 0..3

    float acc[4][4][4];
#pragma unroll
    for (int i = 0; i < 4; i++)
#pragma unroll
        for (int j = 0; j < 4; j++)
#pragma unroll
            for (int c = 0; c < 4; c++) acc[i][j][c] = 0.f;

    auto load_stage = [&](int s, int k0) {
        // A tiles: 128 rows x 4 chunks(16B) x 2 planes
#pragma unroll
        for (int p = 0; p < 2; p++) {
#pragma unroll
            for (int i = 0; i < 2; i++) {
                int c   = tid + i * 256;          // 0..511
                int row = c >> 2, kc = c & 3;
                bf16* dst = sA + (size_t)(s*2+p)*BM*APAD + row*APAD + kc*8;
                cp16(dst, Ap[p] + (size_t)row * lda + k0 + kc*8);
            }
        }
        if (TB) {
#pragma unroll
            for (int p = 0; p < 2; p++) {
#pragma unroll
                for (int i = 0; i < 2; i++) {
                    int c   = tid + i * 256;
                    int row = c >> 2, kc = c & 3;
                    bf16* dst = sB + (size_t)(s*2+p)*BN*APAD + row*APAD + kc*8;
                    cp16(dst, Bp[p] + (size_t)row * ldb + k0 + kc*8);
                }
            }
        } else {
            // 32 k-rows x 16 chunks(16B) x 2 planes
#pragma unroll
            for (int p = 0; p < 2; p++) {
#pragma unroll
                for (int i = 0; i < 2; i++) {
                    int c   = tid + i * 256;      // 0..511
                    int row = c >> 4, kc = c & 15;
                    bf16* dst = sB + (size_t)(s*2+p)*BK*BKPAD + row*BKPAD + kc*8;
                    cp16(dst, Bp[p] + (size_t)(k0+row) * ldb + kc*8);
                }
            }
        }
    };

    const int nk = K / BK;
    load_stage(0, 0);
    cp_commit();

    for (int ks = 0; ks < nk; ks++) {
        const int buf = ks & 1;
        if (ks + 1 < nk) {
            load_stage(buf ^ 1, (ks + 1) * BK);
            cp_commit();
            cp_wait<1>();
        } else {
            cp_wait<0>();
        }
        __syncthreads();

        const bf16* sAh = sA + (size_t)(buf*2+0)*BM*APAD;
        const bf16* sAl = sA + (size_t)(buf*2+1)*BM*APAD;
        const bf16* sBh;
        const bf16* sBl;
        if (TB) { sBh = sB + (size_t)(buf*2+0)*BN*APAD;  sBl = sB + (size_t)(buf*2+1)*BN*APAD; }
        else    { sBh = sB + (size_t)(buf*2+0)*BK*BKPAD; sBl = sB + (size_t)(buf*2+1)*BK*BKPAD; }

#pragma unroll
        for (int kk = 0; kk < 2; kk++) {
            const int ko = kk * 16;

            uint32_t ah[4][4], alr[4][4];
#pragma unroll
            for (int mt = 0; mt < 4; mt++) {
                const int r = wm*64 + mt*16 + g;
                const bf16* p0 = sAh + r*APAD + ko + 2*t;
                ah[mt][0] = *(const uint32_t*)(p0);
                ah[mt][1] = *(const uint32_t*)(p0 + 8*APAD);
                ah[mt][2] = *(const uint32_t*)(p0 + 8);
                ah[mt][3] = *(const uint32_t*)(p0 + 8*APAD + 8);
                const bf16* p1 = sAl + r*APAD + ko + 2*t;
                alr[mt][0] = *(const uint32_t*)(p1);
                alr[mt][1] = *(const uint32_t*)(p1 + 8*APAD);
                alr[mt][2] = *(const uint32_t*)(p1 + 8);
                alr[mt][3] = *(const uint32_t*)(p1 + 8*APAD + 8);
            }

            uint32_t bh[4][2], bl[4][2];
            if (TB) {
#pragma unroll
                for (int nt = 0; nt < 4; nt++) {
                    const int n = wn*32 + nt*8 + g;
                    const bf16* p0 = sBh + n*APAD + ko + 2*t;
                    bh[nt][0] = *(const uint32_t*)(p0);
                    bh[nt][1] = *(const uint32_t*)(p0 + 8);
                    const bf16* p1 = sBl + n*APAD + ko + 2*t;
                    bl[nt][0] = *(const uint32_t*)(p1);
                    bl[nt][1] = *(const uint32_t*)(p1 + 8);
                }
            } else {
#pragma unroll
                for (int nt = 0; nt < 4; nt++) {
                    const int n  = wn*32 + nt*8 + g;
                    const int r0 = ko + 2*t;
                    bh[nt][0] = pack_bf16(sBh[(r0  )*BKPAD + n], sBh[(r0+1)*BKPAD + n]);
                    bh[nt][1] = pack_bf16(sBh[(r0+8)*BKPAD + n], sBh[(r0+9)*BKPAD + n]);
                    bl[nt][0] = pack_bf16(sBl[(r0  )*BKPAD + n], sBl[(r0+1)*BKPAD + n]);
                    bl[nt][1] = pack_bf16(sBl[(r0+8)*BKPAD + n], sBl[(r0+9)*BKPAD + n]);
                }
            }

#pragma unroll
            for (int mt = 0; mt < 4; mt++)
#pragma unroll
                for (int nt = 0; nt < 4; nt++) {
                    mma_bf16(acc[mt][nt], ah[mt],  bh[nt]);
                    mma_bf16(acc[mt][nt], ah[mt],  bl[nt]);
                    mma_bf16(acc[mt][nt], alr[mt], bh[nt]);
                }
        }
        __syncthreads();
    }

    // epilogue
#pragma unroll
    for (int mt = 0; mt < 4; mt++) {
        const int r = m0 + wm*64 + mt*16 + g;
#pragma unroll
        for (int nt = 0; nt < 4; nt++) {
            const int c = n0 + wn*32 + nt*8 + 2*t;
            float2 v0 = make_float2(acc[mt][nt][0], acc[mt][nt][1]);
            float2 v1 = make_float2(acc[mt][nt][2], acc[mt][nt][3]);
            *reinterpret_cast<float2*>(&C[(size_t)r      * ldc + c]) = v0;
            *reinterpret_cast<float2*>(&C[(size_t)(r+8)  * ldc + c]) = v1;
        }
    }
}

// ---------------------------------------------------------------------------
// GEMM kernel wrappers
// ---------------------------------------------------------------------------
__global__ __launch_bounds__(256, 1)
void k_gemm_bt(const bf16* __restrict__ Ah, const bf16* __restrict__ Al, int lda,
               const bf16* __restrict__ Bh, const bf16* __restrict__ Bl, int ldb,
               float* __restrict__ C, int ldc, int K)
{
    gemm_core<true>(Ah, Al, lda, Bh, Bl, ldb, C, ldc, K);
}

__global__ __launch_bounds__(256, 1)
void k_gemm_scores(const bf16* __restrict__ qh, const bf16* __restrict__ ql,
                   const bf16* __restrict__ kh, const bf16* __restrict__ kl,
                   float* __restrict__ S)
{
    const int z = blockIdx.z, b = z >> 4, h = z & 15, kvh = h >> 2;
    const size_t aoff = (size_t)b * L_ * D_ + (size_t)h * HD_;
    const size_t boff = (size_t)b * L_ * (KVH_*HD_) + (size_t)kvh * HD_;
    gemm_core<true>(qh + aoff, ql + aoff, D_,
                    kh + boff, kl + boff, KVH_*HD_,
                    S + (size_t)z * L_ * L_, L_, HD_);
}

__global__ __launch_bounds__(256, 1)
void k_gemm_pv(const bf16* __restrict__ ph, const bf16* __restrict__ pl,
               const bf16* __restrict__ vh, const bf16* __restrict__ vl,
               float* __restrict__ ao)
{
    const int z = blockIdx.z, b = z >> 4, h = z & 15, kvh = h >> 2;
    const size_t boff = (size_t)b * L_ * (KVH_*HD_) + (size_t)kvh * HD_;
    const size_t coff = (size_t)b * L_ * D_ + (size_t)h * HD_;
    gemm_core<false>(ph + (size_t)z * L_ * L_, pl + (size_t)z * L_ * L_, L_,
                     vh + boff, vl + boff, KVH_*HD_,
                     ao + coff, D_, L_);
}

// ---------------------------------------------------------------------------
// fp32 -> (hi, lo) bf16 split
// ---------------------------------------------------------------------------
__device__ __forceinline__ void split1(float x, unsigned short& h, unsigned short& l) {
    bf16 bh = __float2bfloat16(x);
    bf16 bl = __float2bfloat16(x - __bfloat162float(bh));
    h = *reinterpret_cast<unsigned short*>(&bh);
    l = *reinterpret_cast<unsigned short*>(&bl);
}

__global__ void k_split(const float4* __restrict__ X,
                        ushort4* __restrict__ Hi, ushort4* __restrict__ Lo, int n4)
{
    int i = blockIdx.x * blockDim.x + threadIdx.x;
    if (i >= n4) return;
    float4 v = X[i];
    ushort4 hv, lv;
    split1(v.x, hv.x, lv.x);
    split1(v.y, hv.y, lv.y);
    split1(v.z, hv.z, lv.z);
    split1(v.w, hv.w, lv.w);
    Hi[i] = hv;
    Lo[i] = lv;
}

// ---------------------------------------------------------------------------
// RMSNorm + RoPE (unchanged from round 1)
// ---------------------------------------------------------------------------
__global__ void rms_rope_kernel(float* __restrict__ X,
                                const float* __restrict__ gamma,
                                int heads) {
    const int warp = (blockIdx.x * blockDim.x + threadIdx.x) >> 5;
    const int lane = threadIdx.x & 31;
    const int h = warp % heads;
    const int l = (warp / heads) % L_;
    const int b = warp / (heads * L_);

    float* vec = X + ((size_t)(b * L_ + l) * heads + h) * HD_;

    const int p0 = lane, p1 = lane + 32;
    float x0a = vec[2*p0],   x1a = vec[2*p0+1];
    float x0b = vec[2*p1],   x1b = vec[2*p1+1];

    float ss = x0a*x0a + x1a*x1a + x0b*x0b + x1b*x1b;
#pragma unroll
    for (int off = 16; off; off >>= 1)
        ss += __shfl_xor_sync(0xffffffffu, ss, off);

    const float inv = rsqrtf(ss * (1.0f / HD_) + EPS_);
    const float LOG2_THETA = 13.287712379549449f;
    const float fl = (float)l;

    {
        float g0 = gamma[2*p0], g1 = gamma[2*p0+1];
        float re = x0a * inv * g0, im = x1a * inv * g1;
        float fr = fl * exp2f(-(2.0f * p0 / (float)HD_) * LOG2_THETA);
        float s, c; sincosf(fr, &s, &c);
        vec[2*p0]   = re * c - im * s;
        vec[2*p0+1] = re * s + im * c;
    }
    {
        float g0 = gamma[2*p1], g1 = gamma[2*p1+1];
        float re = x0b * inv * g0, im = x1b * inv * g1;
        float fr = fl * exp2f(-(2.0f * p1 / (float)HD_) * LOG2_THETA);
        float s, c; sincosf(fr, &s, &c);
        vec[2*p1]   = re * c - im * s;
        vec[2*p1+1] = re * s + im * c;
    }
}

// ---------------------------------------------------------------------------
// Masked softmax over S rows + split to bf16 P planes. One warp per row.
// ---------------------------------------------------------------------------
__global__ __launch_bounds__(256)
void k_softmax(const float* __restrict__ S, const int* __restrict__ mask,
               bf16* __restrict__ Ph, bf16* __restrict__ Pl)
{
    const int r    = blockIdx.x * 8 + (threadIdx.x >> 5);   // row id
    const int lane = threadIdx.x & 31;
    const int z = r >> 11;          // r / L_
    const int b = z >> 4;

    const float4* row  = reinterpret_cast<const float4*>(S + (size_t)r * L_);
    const int4*   mrow = reinterpret_cast<const int4*>(mask + (size_t)b * L_);
    const float sc = 0.08838834764831845f;   // 1/sqrt(128)

    float m = -CUDART_INF_F;
#pragma unroll 4
    for (int i = lane; i < L_/4; i += 32) {
        float4 v = row[i]; int4 mk = mrow[i];
        if (mk.x) m = fmaxf(m, v.x * sc);
        if (mk.y) m = fmaxf(m, v.y * sc);
        if (mk.z) m = fmaxf(m, v.z * sc);
        if (mk.w) m = fmaxf(m, v.w * sc);
    }
#pragma unroll
    for (int off = 16; off; off >>= 1)
        m = fmaxf(m, __shfl_xor_sync(0xffffffffu, m, off));

    float s = 0.f;
#pragma unroll 4
    for (int i = lane; i < L_/4; i += 32) {
        float4 v = row[i]; int4 mk = mrow[i];
        if (mk.x) s += __expf(v.x * sc - m);
        if (mk.y) s += __expf(v.y * sc - m);
        if (mk.z) s += __expf(v.z * sc - m);
        if (mk.w) s += __expf(v.w * sc - m);
    }
#pragma unroll
    for (int off = 16; off; off >>= 1)
        s += __shfl_xor_sync(0xffffffffu, s, off);

    const float inv = (s > 0.f) ? 1.f / s : 0.f;

    ushort4* ph = reinterpret_cast<ushort4*>(Ph + (size_t)r * L_);
    ushort4* pl = reinterpret_cast<ushort4*>(Pl + (size_t)r * L_);
#pragma unroll 4
    for (int i = lane; i < L_/4; i += 32) {
        float4 v = row[i]; int4 mk = mrow[i];
        float p0 = mk.x ? __expf(v.x * sc - m) * inv : 0.f;
        float p1 = mk.y ? __expf(v.y * sc - m) * inv : 0.f;
        float p2 = mk.z ? __expf(v.z * sc - m) * inv : 0.f;
        float p3 = mk.w ? __expf(v.w * sc - m) * inv : 0.f;
        ushort4 hv, lv;
        split1(p0, hv.x, lv.x);
        split1(p1, hv.y, lv.y);
        split1(p2, hv.z, lv.z);
        split1(p3, hv.w, lv.w);
        ph[i] = hv;
        pl[i] = lv;
    }
}

// ---------------------------------------------------------------------------
// Launch
// ---------------------------------------------------------------------------
extern "C" void kernel_launch(void* const* d_in, const int* in_sizes, int n_in,
                              void* d_out, int out_size) {
    const float* x    = (const float*)d_in[0];
    const int*   mask = (const int*)  d_in[1];
    const float* Wq   = (const float*)d_in[2];
    const float* Wk   = (const float*)d_in[3];
    const float* Wv   = (const float*)d_in[4];
    const float* Wo   = (const float*)d_in[5];
    const float* qg   = (const float*)d_in[6];
    const float* kg   = (const float*)d_in[7];
    float* out = (float*)d_out;

    float *q, *k, *v, *ao, *S;
    bf16 *xh, *xl, *wqh, *wql, *wkh, *wkl, *wvh, *wvl, *woh, *wol;
    bf16 *qh, *ql, *kh, *kl, *vh, *vl, *Ph, *Pl, *aoh, *aol;
    cudaGetSymbolAddress((void**)&q,   g_q);
    cudaGetSymbolAddress((void**)&k,   g_k);
    cudaGetSymbolAddress((void**)&v,   g_v);
    cudaGetSymbolAddress((void**)&ao,  g_ao);
    cudaGetSymbolAddress((void**)&S,   g_S);
    cudaGetSymbolAddress((void**)&xh,  g_xh);  cudaGetSymbolAddress((void**)&xl,  g_xl);
    cudaGetSymbolAddress((void**)&wqh, g_wqh); cudaGetSymbolAddress((void**)&wql, g_wql);
    cudaGetSymbolAddress((void**)&wkh, g_wkh); cudaGetSymbolAddress((void**)&wkl, g_wkl);
    cudaGetSymbolAddress((void**)&wvh, g_wvh); cudaGetSymbolAddress((void**)&wvl, g_wvl);
    cudaGetSymbolAddress((void**)&woh, g_woh); cudaGetSymbolAddress((void**)&wol, g_wol);
    cudaGetSymbolAddress((void**)&qh,  g_qh);  cudaGetSymbolAddress((void**)&ql,  g_ql);
    cudaGetSymbolAddress((void**)&kh,  g_kh);  cudaGetSymbolAddress((void**)&kl,  g_kl);
    cudaGetSymbolAddress((void**)&vh,  g_vh);  cudaGetSymbolAddress((void**)&vl,  g_vl);
    cudaGetSymbolAddress((void**)&Ph,  g_Ph);  cudaGetSymbolAddress((void**)&Pl,  g_Pl);
    cudaGetSymbolAddress((void**)&aoh, g_aoh); cudaGetSymbolAddress((void**)&aol, g_aol);

    cudaFuncSetAttribute(k_gemm_bt,     cudaFuncAttributeMaxDynamicSharedMemorySize, SMEM_TB_BYTES);
    cudaFuncSetAttribute(k_gemm_scores, cudaFuncAttributeMaxDynamicSharedMemorySize, SMEM_TB_BYTES);
    cudaFuncSetAttribute(k_gemm_pv,     cudaFuncAttributeMaxDynamicSharedMemorySize, SMEM_KM_BYTES);

    const int M = B_ * L_;        // 4096
    dim3 blk(256);

    auto launch_split = [&](const float* src, bf16* hi, bf16* lo, int n) {
        int n4 = n / 4;
        k_split<<<(n4 + 255) / 256, 256>>>((const float4*)src, (ushort4*)hi, (ushort4*)lo, n4);
    };

    // input/weight splits
    launch_split(x,  xh,  xl,  M * D_);
    launch_split(Wq, wqh, wql, D_ * D_);
    launch_split(Wk, wkh, wkl, KVH_ * HD_ * D_);
    launch_split(Wv, wvh, wvl, KVH_ * HD_ * D_);
    launch_split(Wo, woh, wol, D_ * D_);

    // projections (bf16x3 tensor-core GEMM)
    k_gemm_bt<<<dim3(D_/BN,          M/BM), blk, SMEM_TB_BYTES>>>(xh, xl, D_, wqh, wql, D_, q, D_,          D_);
    k_gemm_bt<<<dim3((KVH_*HD_)/BN,  M/BM), blk, SMEM_TB_BYTES>>>(xh, xl, D_, wkh, wkl, D_, k, KVH_*HD_,    D_);
    k_gemm_bt<<<dim3((KVH_*HD_)/BN,  M/BM), blk, SMEM_TB_BYTES>>>(xh, xl, D_, wvh, wvl, D_, v, KVH_*HD_,    D_);

    // rmsnorm + rope (fp32, in place)
    rms_rope_kernel<<<(B_ * L_ * H_)   / 8, 256>>>(q, qg, H_);
    rms_rope_kernel<<<(B_ * L_ * KVH_) / 8, 256>>>(k, kg, KVH_);

    // q/k/v splits
    launch_split(q, qh, ql, M * D_);
    launch_split(k, kh, kl, B_ * L_ * KVH_ * HD_);
    launch_split(v, vh, vl, B_ * L_ * KVH_ * HD_);

    // scores S = q k^T (batched over b,h)
    k_gemm_scores<<<dim3(L_/BN, L_/BM, B_*H_), blk, SMEM_TB_BYTES>>>(qh, ql, kh, kl, S);

    // masked softmax + split to P
    k_softmax<<<(B_*H_*L_)/8, 256>>>(S, mask, Ph, Pl);

    // attention output = P v (batched)
    k_gemm_pv<<<dim3(HD_/BN, L_/BM, B_*H_), blk, SMEM_KM_BYTES>>>(Ph, Pl, vh, vl, ao);

    // output projection
    launch_split(ao, aoh, aol, M * D_);
    k_gemm_bt<<<dim3(D_/BN, M/BM), blk, SMEM_TB_BYTES>>>(aoh, aol, D_, woh, wol, D_, out, D_, D_);
}

// round 3
// speedup vs baseline: 4.0283x; 1.2267x over previous
#include <cuda_runtime.h>
#include <cuda_bf16.h>
#include <math.h>
#include <math_constants.h>
#include <stdint.h>

#define B_    2
#define L_    2048
#define D_    2048
#define H_    16
#define KVH_  4
#define HD_   128
#define EPS_  1e-6f

typedef __nv_bfloat16 bf16;

// ---------------------------------------------------------------------------
// Static scratch
// ---------------------------------------------------------------------------
__device__ float g_q [B_*L_*D_];
__device__ float g_k [B_*L_*KVH_*HD_];
__device__ float g_v [B_*L_*KVH_*HD_];

__device__ bf16 g_xh [B_*L_*D_],      g_xl [B_*L_*D_];
__device__ bf16 g_wqh[D_*D_],         g_wql[D_*D_];
__device__ bf16 g_wkh[KVH_*HD_*D_],   g_wkl[KVH_*HD_*D_];
__device__ bf16 g_wvh[KVH_*HD_*D_],   g_wvl[KVH_*HD_*D_];
__device__ bf16 g_woh[D_*D_],         g_wol[D_*D_];
__device__ bf16 g_qh [B_*L_*D_],      g_ql [B_*L_*D_];
__device__ bf16 g_kh [B_*L_*KVH_*HD_],g_kl [B_*L_*KVH_*HD_];
__device__ bf16 g_vth[B_*KVH_*HD_*L_],g_vtl[B_*KVH_*HD_*L_];   // V transposed [b][kvh][d][L]
__device__ bf16 g_aoh[B_*L_*D_],      g_aol[B_*L_*D_];

// ---------------------------------------------------------------------------
// PTX helpers
// ---------------------------------------------------------------------------
__device__ __forceinline__ void mma_bf16(float* c, const uint32_t* a, const uint32_t* b) {
    asm volatile(
        "mma.sync.aligned.m16n8k16.row.col.f32.bf16.bf16.f32 "
        "{%0,%1,%2,%3}, {%4,%5,%6,%7}, {%8,%9}, {%0,%1,%2,%3};\n"
        : "+f"(c[0]), "+f"(c[1]), "+f"(c[2]), "+f"(c[3])
        : "r"(a[0]), "r"(a[1]), "r"(a[2]), "r"(a[3]), "r"(b[0]), "r"(b[1]));
}

__device__ __forceinline__ void cp16(const bf16* dst_s, const bf16* src_g) {
    uint32_t d = (uint32_t)__cvta_generic_to_shared(dst_s);
    asm volatile("cp.async.cg.shared.global [%0], [%1], 16;\n"
                 :: "r"(d), "l"(src_g) : "memory");
}
__device__ __forceinline__ void cp_commit() {
    asm volatile("cp.async.commit_group;\n" ::: "memory");
}
template<int N>
__device__ __forceinline__ void cp_wait() {
    asm volatile("cp.async.wait_group %0;\n" :: "n"(N) : "memory");
}

__device__ __forceinline__ uint32_t pack2(bf16 a, bf16 b) {
    uint32_t x = *reinterpret_cast<unsigned short*>(&a);
    uint32_t y = *reinterpret_cast<unsigned short*>(&b);
    return x | (y << 16);
}

__device__ __forceinline__ void split1(float x, unsigned short& h, unsigned short& l) {
    bf16 bh = __float2bfloat16(x);
    bf16 bl = __float2bfloat16(x - __bfloat162float(bh));
    h = *reinterpret_cast<unsigned short*>(&bh);
    l = *reinterpret_cast<unsigned short*>(&bl);
}

// ---------------------------------------------------------------------------
// Projection GEMM: C[M,N] fp32 = (Ah+Al)[M,K] * (Bh+Bl)[N,K]^T, bf16x3
// ---------------------------------------------------------------------------
#define BM 128
#define BN 128
#define BK 32
#define APAD 40

#define SM_A_HALVES (2*2*BM*APAD)
#define SM_B_HALVES (2*2*BN*APAD)
#define SMEM_TB_BYTES ((SM_A_HALVES + SM_B_HALVES)*2)   // 81920

__global__ __launch_bounds__(256, 1)
void k_gemm_bt(const bf16* __restrict__ Ah, const bf16* __restrict__ Al, int lda,
               const bf16* __restrict__ Bh, const bf16* __restrict__ Bl, int ldb,
               float* __restrict__ C, int ldc, int K)
{
    extern __shared__ bf16 sh[];
    bf16* sA = sh;
    bf16* sB = sh + SM_A_HALVES;

    const int tid = threadIdx.x;
    const int m0 = blockIdx.y * BM;
    const int n0 = blockIdx.x * BN;

    const bf16* Ap[2] = { Ah + (size_t)m0 * lda, Al + (size_t)m0 * lda };
    const bf16* Bp[2] = { Bh + (size_t)n0 * ldb, Bl + (size_t)n0 * ldb };

    const int lane = tid & 31;
    const int g    = lane >> 2;
    const int t    = lane & 3;
    const int warp = tid >> 5;
    const int wm   = warp >> 2;
    const int wn   = warp & 3;

    float acc[4][4][4];
#pragma unroll
    for (int i = 0; i < 4; i++)
#pragma unroll
        for (int j = 0; j < 4; j++)
#pragma unroll
            for (int c = 0; c < 4; c++) acc[i][j][c] = 0.f;

    auto load_stage = [&](int s, int k0) {
#pragma unroll
        for (int p = 0; p < 2; p++) {
#pragma unroll
            for (int i = 0; i < 2; i++) {
                int c   = tid + i * 256;
                int row = c >> 2, kc = c & 3;
                cp16(sA + (size_t)(s*2+p)*BM*APAD + row*APAD + kc*8,
                     Ap[p] + (size_t)row * lda + k0 + kc*8);
            }
#pragma unroll
            for (int i = 0; i < 2; i++) {
                int c   = tid + i * 256;
                int row = c >> 2, kc = c & 3;
                cp16(sB + (size_t)(s*2+p)*BN*APAD + row*APAD + kc*8,
                     Bp[p] + (size_t)row * ldb + k0 + kc*8);
            }
        }
    };

    const int nk = K / BK;
    load_stage(0, 0);
    cp_commit();

    for (int ks = 0; ks < nk; ks++) {
        const int buf = ks & 1;
        if (ks + 1 < nk) {
            load_stage(buf ^ 1, (ks + 1) * BK);
            cp_commit();
            cp_wait<1>();
        } else {
            cp_wait<0>();
        }
        __syncthreads();

        const bf16* sAh = sA + (size_t)(buf*2+0)*BM*APAD;
        const bf16* sAl = sA + (size_t)(buf*2+1)*BM*APAD;
        const bf16* sBh = sB + (size_t)(buf*2+0)*BN*APAD;
        const bf16* sBl = sB + (size_t)(buf*2+1)*BN*APAD;

#pragma unroll
        for (int kk = 0; kk < 2; kk++) {
            const int ko = kk * 16;

            uint32_t ah[4][4], alr[4][4];
#pragma unroll
            for (int mt = 0; mt < 4; mt++) {
                const int r = wm*64 + mt*16 + g;
                const bf16* p0 = sAh + r*APAD + ko + 2*t;
                ah[mt][0] = *(const uint32_t*)(p0);
                ah[mt][1] = *(const uint32_t*)(p0 + 8*APAD);
                ah[mt][2] = *(const uint32_t*)(p0 + 8);
                ah[mt][3] = *(const uint32_t*)(p0 + 8*APAD + 8);
                const bf16* p1 = sAl + r*APAD + ko + 2*t;
                alr[mt][0] = *(const uint32_t*)(p1);
                alr[mt][1] = *(const uint32_t*)(p1 + 8*APAD);
                alr[mt][2] = *(const uint32_t*)(p1 + 8);
                alr[mt][3] = *(const uint32_t*)(p1 + 8*APAD + 8);
            }

            uint32_t bh[4][2], bl[4][2];
#pragma unroll
            for (int nt = 0; nt < 4; nt++) {
                const int n = wn*32 + nt*8 + g;
                const bf16* p0 = sBh + n*APAD + ko + 2*t;
                bh[nt][0] = *(const uint32_t*)(p0);
                bh[nt][1] = *(const uint32_t*)(p0 + 8);
                const bf16* p1 = sBl + n*APAD + ko + 2*t;
                bl[nt][0] = *(const uint32_t*)(p1);
                bl[nt][1] = *(const uint32_t*)(p1 + 8);
            }

#pragma unroll
            for (int mt = 0; mt < 4; mt++)
#pragma unroll
                for (int nt = 0; nt < 4; nt++) {
                    mma_bf16(acc[mt][nt], ah[mt],  bh[nt]);
                    mma_bf16(acc[mt][nt], ah[mt],  bl[nt]);
                    mma_bf16(acc[mt][nt], alr[mt], bh[nt]);
                }
        }
        __syncthreads();
    }

#pragma unroll
    for (int mt = 0; mt < 4; mt++) {
        const int r = m0 + wm*64 + mt*16 + g;
#pragma unroll
        for (int nt = 0; nt < 4; nt++) {
            const int c = n0 + wn*32 + nt*8 + 2*t;
            *reinterpret_cast<float2*>(&C[(size_t)r     * ldc + c]) =
                make_float2(acc[mt][nt][0], acc[mt][nt][1]);
            *reinterpret_cast<float2*>(&C[(size_t)(r+8) * ldc + c]) =
                make_float2(acc[mt][nt][2], acc[mt][nt][3]);
        }
    }
}

// ---------------------------------------------------------------------------
// fp32 -> (hi, lo) split (x, weights)
// ---------------------------------------------------------------------------
__global__ void k_split(const float4* __restrict__ X,
                        ushort4* __restrict__ Hi, ushort4* __restrict__ Lo, int n4)
{
    int i = blockIdx.x * blockDim.x + threadIdx.x;
    if (i >= n4) return;
    float4 v = X[i];
    ushort4 hv, lv;
    split1(v.x, hv.x, lv.x);
    split1(v.y, hv.y, lv.y);
    split1(v.z, hv.z, lv.z);
    split1(v.w, hv.w, lv.w);
    Hi[i] = hv;
    Lo[i] = lv;
}

// ---------------------------------------------------------------------------
// RMSNorm + RoPE, fp32 in -> bf16 hi/lo planes out. One warp per (b,l,h).
// ---------------------------------------------------------------------------
__global__ void rms_rope_split_kernel(const float* __restrict__ X,
                                      const float* __restrict__ gamma,
                                      bf16* __restrict__ Xh, bf16* __restrict__ Xl,
                                      int heads) {
    const int warp = (blockIdx.x * blockDim.x + threadIdx.x) >> 5;
    const int lane = threadIdx.x & 31;
    const int h = warp % heads;
    const int l = (warp / heads) % L_;
    const int b = warp / (heads * L_);

    const size_t base = ((size_t)(b * L_ + l) * heads + h) * HD_;
    const float* vec = X + base;

    const int p0 = lane, p1 = lane + 32;
    float x0a = vec[2*p0],   x1a = vec[2*p0+1];
    float x0b = vec[2*p1],   x1b = vec[2*p1+1];

    float ss = x0a*x0a + x1a*x1a + x0b*x0b + x1b*x1b;
#pragma unroll
    for (int off = 16; off; off >>= 1)
        ss += __shfl_xor_sync(0xffffffffu, ss, off);

    const float inv = rsqrtf(ss * (1.0f / HD_) + EPS_);
    const float LOG2_THETA = 13.287712379549449f;
    const float fl = (float)l;

    unsigned short hh, ll;
    {
        float g0 = gamma[2*p0], g1 = gamma[2*p0+1];
        float re = x0a * inv * g0, im = x1a * inv * g1;
        float fr = fl * exp2f(-(2.0f * p0 / (float)HD_) * LOG2_THETA);
        float s, c; sincosf(fr, &s, &c);
        float o0 = re * c - im * s, o1 = re * s + im * c;
        split1(o0, hh, ll);
        ((unsigned short*)Xh)[base + 2*p0] = hh; ((unsigned short*)Xl)[base + 2*p0] = ll;
        split1(o1, hh, ll);
        ((unsigned short*)Xh)[base + 2*p0+1] = hh; ((unsigned short*)Xl)[base + 2*p0+1] = ll;
    }
    {
        float g0 = gamma[2*p1], g1 = gamma[2*p1+1];
        float re = x0b * inv * g0, im = x1b * inv * g1;
        float fr = fl * exp2f(-(2.0f * p1 / (float)HD_) * LOG2_THETA);
        float s, c; sincosf(fr, &s, &c);
        float o0 = re * c - im * s, o1 = re * s + im * c;
        split1(o0, hh, ll);
        ((unsigned short*)Xh)[base + 2*p1] = hh; ((unsigned short*)Xl)[base + 2*p1] = ll;
        split1(o1, hh, ll);
        ((unsigned short*)Xh)[base + 2*p1+1] = hh; ((unsigned short*)Xl)[base + 2*p1+1] = ll;
    }
}

// ---------------------------------------------------------------------------
// V transpose + split: v fp32 [b][l][kvh][d] -> vth/vtl bf16 [b][kvh][d][L]
// ---------------------------------------------------------------------------
__global__ void k_vtrans(const float* __restrict__ V,
                         bf16* __restrict__ Vth, bf16* __restrict__ Vtl)
{
    __shared__ float tile[32][33];
    const int tx = threadIdx.x & 31;
    const int ty = threadIdx.x >> 5;        // 0..7
    const int l0 = blockIdx.x * 32;
    const int d0 = blockIdx.y * 32;
    const int z  = blockIdx.z;
    const int b  = z >> 2, kvh = z & 3;

#pragma unroll
    for (int i = 0; i < 4; i++) {
        int l = l0 + ty + i*8;
        tile[ty + i*8][tx] =
            V[((size_t)(b*L_ + l) * KVH_ + kvh) * HD_ + d0 + tx];
    }
    __syncthreads();
#pragma unroll
    for (int i = 0; i < 4; i++) {
        int d = d0 + ty + i*8;
        float val = tile[tx][ty + i*8];
        unsigned short hh, ll;
        split1(val, hh, ll);
        size_t idx = ((size_t)(b*KVH_ + kvh) * HD_ + d) * L_ + l0 + tx;
        ((unsigned short*)Vth)[idx] = hh;
        ((unsigned short*)Vtl)[idx] = ll;
    }
}

// ---------------------------------------------------------------------------
// Fused flash attention, bf16x3 MMA, online softmax on fragments.
// Block: (q-tile 128, head, batch). 256 threads = 8 warps, 16 q-rows each.
// ---------------------------------------------------------------------------
#define QPAD 136     // halves/row, conflict-free (word stride 68 -> 4g+t)
#define VPAD 72      // halves/row (word stride 36 -> 4g+t)

#define QPL  (128*QPAD)           // 17408 halves/plane
#define KPL  (64*QPAD)            // 8704
#define KBUF (2*KPL)              // 17408
#define VPL  (128*VPAD)           // 9216
#define VBUF (2*VPL)              // 18432
#define QS_OFF 0
#define KS_OFF (2*QPL)            // 34816
#define VS_OFF (KS_OFF + 2*KBUF)  // 69632
#define MS_OFF_H (VS_OFF + 2*VBUF) // 106496 halves
#define FA_SMEM_BYTES (MS_OFF_H*2 + 2*64*4)   // 213504

__global__ __launch_bounds__(256, 1)
void k_flash(const bf16* __restrict__ qh, const bf16* __restrict__ ql,
             const bf16* __restrict__ kh, const bf16* __restrict__ kl,
             const bf16* __restrict__ vth, const bf16* __restrict__ vtl,
             const int* __restrict__ mask,
             bf16* __restrict__ aoh, bf16* __restrict__ aol)
{
    extern __shared__ bf16 sm[];
    bf16*  Qs = sm + QS_OFF;
    bf16*  Ks = sm + KS_OFF;
    bf16*  Vs = sm + VS_OFF;
    float* Ms = (float*)(sm + MS_OFF_H);

    const int tid  = threadIdx.x;
    const int lane = tid & 31;
    const int g    = lane >> 2;
    const int t    = lane & 3;
    const int w    = tid >> 5;

    const int qt = blockIdx.x, h = blockIdx.y, b = blockIdx.z;
    const int kvh = h >> 2;
    const int q0  = qt * 128;

    const bf16* Qg[2] = { qh + ((size_t)(b*L_ + q0)) * D_ + h * HD_,
                          ql + ((size_t)(b*L_ + q0)) * D_ + h * HD_ };
    const bf16* Kg[2] = { kh + ((size_t)(b*L_)) * (KVH_*HD_) + kvh * HD_,
                          kl + ((size_t)(b*L_)) * (KVH_*HD_) + kvh * HD_ };
    const bf16* Vg[2] = { vth + ((size_t)(b*KVH_ + kvh)) * HD_ * L_,
                          vtl + ((size_t)(b*KVH_ + kvh)) * HD_ * L_ };

    // ---- Q load (once) ----
#pragma unroll
    for (int p = 0; p < 2; p++)
#pragma unroll
        for (int i = 0; i < 8; i++) {
            int c = tid + i * 256;           // 0..2047
            int row = c >> 4, ch = c & 15;
            cp16(Qs + p*QPL + row*QPAD + ch*8, Qg[p] + (size_t)row * D_ + ch*8);
        }

    auto load_stage = [&](int s, int kt) {
        const int j0 = kt * 64;
#pragma unroll
        for (int p = 0; p < 2; p++) {
#pragma unroll
            for (int i = 0; i < 4; i++) {
                int c = tid + i * 256;       // 0..1023
                int row = c >> 4, ch = c & 15;
                cp16(Ks + s*KBUF + p*KPL + row*QPAD + ch*8,
                     Kg[p] + (size_t)(j0 + row) * (KVH_*HD_) + ch*8);
            }
#pragma unroll
            for (int i = 0; i < 4; i++) {
                int c = tid + i * 256;       // 0..1023
                int row = c >> 3, ch = c & 7;
                cp16(Vs + s*VBUF + p*VPL + row*VPAD + ch*8,
                     Vg[p] + (size_t)row * L_ + j0 + ch*8);
            }
        }
        if (tid < 64)
            Ms[s*64 + tid] = mask[b*L_ + j0 + tid] ? 0.f : -1e30f;
    };

    load_stage(0, 0);
    cp_commit();

    float o[16][4];
#pragma unroll
    for (int i = 0; i < 16; i++)
#pragma unroll
        for (int c = 0; c < 4; c++) o[i][c] = 0.f;

    float mprev0 = -1e30f, mprev1 = -1e30f;
    float lsum0 = 0.f, lsum1 = 0.f;
    const float sc = 0.08838834764831845f;

    const int NT = L_ / 64;
    for (int kt = 0; kt < NT; kt++) {
        const int buf = kt & 1;
        if (kt + 1 < NT) {
            load_stage(buf ^ 1, kt + 1);
            cp_commit();
            cp_wait<1>();
        } else {
            cp_wait<0>();
        }
        __syncthreads();

        // ---- S = Q K^T : per warp m16 x n64 x k128 ----
        float s[8][4];
#pragma unroll
        for (int nt = 0; nt < 8; nt++)
#pragma unroll
            for (int c = 0; c < 4; c++) s[nt][c] = 0.f;

        const bf16* qbh = Qs + (w*16 + g)*QPAD + 2*t;
        const bf16* qbl = qbh + QPL;
        const bf16* kbh = Ks + buf*KBUF + g*QPAD + 2*t;
        const bf16* kbl = kbh + KPL;

#pragma unroll
        for (int kk = 0; kk < 8; kk++) {
            const int ko = kk * 16;
            uint32_t ah[4], al[4];
            ah[0] = *(const uint32_t*)(qbh + ko);
            ah[1] = *(const uint32_t*)(qbh + ko + 8*QPAD);
            ah[2] = *(const uint32_t*)(qbh + ko + 8);
            ah[3] = *(const uint32_t*)(qbh + ko + 8*QPAD + 8);
            al[0] = *(const uint32_t*)(qbl + ko);
            al[1] = *(const uint32_t*)(qbl + ko + 8*QPAD);
            al[2] = *(const uint32_t*)(qbl + ko + 8);
            al[3] = *(const uint32_t*)(qbl + ko + 8*QPAD + 8);
#pragma unroll
            for (int nt = 0; nt < 8; nt++) {
                uint32_t bh[2], bl[2];
                const bf16* pk = kbh + nt*8*QPAD + ko;
                bh[0] = *(const uint32_t*)(pk);
                bh[1] = *(const uint32_t*)(pk + 8);
                const bf16* pl = kbl + nt*8*QPAD + ko;
                bl[0] = *(const uint32_t*)(pl);
                bl[1] = *(const uint32_t*)(pl + 8);
                mma_bf16(s[nt], ah, bh);
                mma_bf16(s[nt], ah, bl);
                mma_bf16(s[nt], al, bh);
            }
        }

        // ---- online softmax on fragments ----
        const float* msf = Ms + buf*64;
        float m0 = -1e30f, m1 = -1e30f;
#pragma unroll
        for (int nt = 0; nt < 8; nt++) {
            float b0 = msf[8*nt + 2*t], b1 = msf[8*nt + 2*t + 1];
            s[nt][0] = s[nt][0]*sc + b0;
            s[nt][1] = s[nt][1]*sc + b1;
            s[nt][2] = s[nt][2]*sc + b0;
            s[nt][3] = s[nt][3]*sc + b1;
            m0 = fmaxf(m0, fmaxf(s[nt][0], s[nt][1]));
            m1 = fmaxf(m1, fmaxf(s[nt][2], s[nt][3]));
        }
        m0 = fmaxf(m0, __shfl_xor_sync(0xffffffffu, m0, 1));
        m0 = fmaxf(m0, __shfl_xor_sync(0xffffffffu, m0, 2));
        m1 = fmaxf(m1, __shfl_xor_sync(0xffffffffu, m1, 1));
        m1 = fmaxf(m1, __shfl_xor_sync(0xffffffffu, m1, 2));

        const float mn0 = fmaxf(mprev0, m0);
        const float mn1 = fmaxf(mprev1, m1);
        const float alpha0 = __expf(mprev0 - mn0);
        const float alpha1 = __expf(mprev1 - mn1);
        mprev0 = mn0; mprev1 = mn1;

        float sum0 = 0.f, sum1 = 0.f;
#pragma unroll
        for (int nt = 0; nt < 8; nt++) {
            s[nt][0] = __expf(s[nt][0] - mn0);
            s[nt][1] = __expf(s[nt][1] - mn0);
            s[nt][2] = __expf(s[nt][2] - mn1);
            s[nt][3] = __expf(s[nt][3] - mn1);
            sum0 += s[nt][0] + s[nt][1];
            sum1 += s[nt][2] + s[nt][3];
        }
        sum0 += __shfl_xor_sync(0xffffffffu, sum0, 1);
        sum0 += __shfl_xor_sync(0xffffffffu, sum0, 2);
        sum1 += __shfl_xor_sync(0xffffffffu, sum1, 1);
        sum1 += __shfl_xor_sync(0xffffffffu, sum1, 2);
        lsum0 = lsum0 * alpha0 + sum0;
        lsum1 = lsum1 * alpha1 + sum1;

#pragma unroll
        for (int nt = 0; nt < 16; nt++) {
            o[nt][0] *= alpha0; o[nt][1] *= alpha0;
            o[nt][2] *= alpha1; o[nt][3] *= alpha1;
        }

        // ---- P fragments (register-local split to bf16 hi/lo) ----
        uint32_t pah[4][4], pal[4][4];
#pragma unroll
        for (int kk = 0; kk < 4; kk++) {
            const int n0t = 2*kk, n1t = 2*kk + 1;
            float p00 = s[n0t][0], p01 = s[n0t][1], p02 = s[n0t][2], p03 = s[n0t][3];
            float p10 = s[n1t][0], p11 = s[n1t][1], p12 = s[n1t][2], p13 = s[n1t][3];
            bf16 h00 = __float2bfloat16(p00), h01 = __float2bfloat16(p01);
            bf16 h02 = __float2bfloat16(p02), h03 = __float2bfloat16(p03);
            bf16 h10 = __float2bfloat16(p10), h11 = __float2bfloat16(p11);
            bf16 h12 = __float2bfloat16(p12), h13 = __float2bfloat16(p13);
            pah[kk][0] = pack2(h00, h01);
            pah[kk][1] = pack2(h02, h03);
            pah[kk][2] = pack2(h10, h11);
            pah[kk][3] = pack2(h12, h13);
            pal[kk][0] = pack2(__float2bfloat16(p00 - __bfloat162float(h00)),
                               __float2bfloat16(p01 - __bfloat162float(h01)));
            pal[kk][1] = pack2(__float2bfloat16(p02 - __bfloat162float(h02)),
                               __float2bfloat16(p03 - __bfloat162float(h03)));
            pal[kk][2] = pack2(__float2bfloat16(p10 - __bfloat162float(h10)),
                               __float2bfloat16(p11 - __bfloat162float(h11)));
            pal[kk][3] = pack2(__float2bfloat16(p12 - __bfloat162float(h12)),
                               __float2bfloat16(p13 - __bfloat162float(h13)));
        }

        // ---- O += P V : per warp m16 x n128 x k64 ----
        const bf16* vbh = Vs + buf*VBUF + g*VPAD + 2*t;
        const bf16* vbl = vbh + VPL;
#pragma unroll
        for (int kk = 0; kk < 4; kk++) {
            const int ko = kk * 16;
#pragma unroll
            for (int nt = 0; nt < 16; nt++) {
                uint32_t bh[2], bl[2];
                const bf16* pv = vbh + nt*8*VPAD + ko;
                bh[0] = *(const uint32_t*)(pv);
                bh[1] = *(const uint32_t*)(pv + 8);
                const bf16* pl = vbl + nt*8*VPAD + ko;
                bl[0] = *(const uint32_t*)(pl);
                bl[1] = *(const uint32_t*)(pl + 8);
                mma_bf16(o[nt], pah[kk], bh);
                mma_bf16(o[nt], pah[kk], bl);
                mma_bf16(o[nt], pal[kk], bh);
            }
        }
        __syncthreads();
    }

    // ---- epilogue: normalize, split, store bf16 hi/lo ----
    const float inv0 = lsum0 > 0.f ? 1.f / lsum0 : 0.f;
    const float inv1 = lsum1 > 0.f ? 1.f / lsum1 : 0.f;
    const int row0 = q0 + w*16 + g;
    const size_t base0 = (size_t)(b*L_ + row0) * D_ + h * HD_;
    const size_t base1 = base0 + 8 * (size_t)D_;

#pragma unroll
    for (int nt = 0; nt < 16; nt++) {
        const int col = nt*8 + 2*t;
        float v0 = o[nt][0] * inv0, v1 = o[nt][1] * inv0;
        float v2 = o[nt][2] * inv1, v3 = o[nt][3] * inv1;
        bf16 h0 = __float2bfloat16(v0), h1 = __float2bfloat16(v1);
        bf16 h2 = __float2bfloat16(v2), h3 = __float2bfloat16(v3);
        *(uint32_t*)(aoh + base0 + col) = pack2(h0, h1);
        *(uint32_t*)(aoh + base1 + col) = pack2(h2, h3);
        *(uint32_t*)(aol + base0 + col) =
            pack2(__float2bfloat16(v0 - __bfloat162float(h0)),
                  __float2bfloat16(v1 - __bfloat162float(h1)));
        *(uint32_t*)(aol + base1 + col) =
            pack2(__float2bfloat16(v2 - __bfloat162float(h2)),
                  __float2bfloat16(v3 - __bfloat162float(h3)));
    }
}

// ---------------------------------------------------------------------------
// Launch
// ---------------------------------------------------------------------------
extern "C" void kernel_launch(void* const* d_in, const int* in_sizes, int n_in,
                              void* d_out, int out_size) {
    const float* x    = (const float*)d_in[0];
    const int*   mask = (const int*)  d_in[1];
    const float* Wq   = (const float*)d_in[2];
    const float* Wk   = (const float*)d_in[3];
    const float* Wv   = (const float*)d_in[4];
    const float* Wo   = (const float*)d_in[5];
    const float* qg   = (const float*)d_in[6];
    const float* kg   = (const float*)d_in[7];
    float* out = (float*)d_out;

    float *q, *k, *v;
    bf16 *xh, *xl, *wqh, *wql, *wkh, *wkl, *wvh, *wvl, *woh, *wol;
    bf16 *qhp, *qlp, *khp, *klp, *vth, *vtl, *aoh, *aol;
    cudaGetSymbolAddress((void**)&q,   g_q);
    cudaGetSymbolAddress((void**)&k,   g_k);
    cudaGetSymbolAddress((void**)&v,   g_v);
    cudaGetSymbolAddress((void**)&xh,  g_xh);  cudaGetSymbolAddress((void**)&xl,  g_xl);
    cudaGetSymbolAddress((void**)&wqh, g_wqh); cudaGetSymbolAddress((void**)&wql, g_wql);
    cudaGetSymbolAddress((void**)&wkh, g_wkh); cudaGetSymbolAddress((void**)&wkl, g_wkl);
    cudaGetSymbolAddress((void**)&wvh, g_wvh); cudaGetSymbolAddress((void**)&wvl, g_wvl);
    cudaGetSymbolAddress((void**)&woh, g_woh); cudaGetSymbolAddress((void**)&wol, g_wol);
    cudaGetSymbolAddress((void**)&qhp, g_qh);  cudaGetSymbolAddress((void**)&qlp, g_ql);
    cudaGetSymbolAddress((void**)&khp, g_kh);  cudaGetSymbolAddress((void**)&klp, g_kl);
    cudaGetSymbolAddress((void**)&vth, g_vth); cudaGetSymbolAddress((void**)&vtl, g_vtl);
    cudaGetSymbolAddress((void**)&aoh, g_aoh); cudaGetSymbolAddress((void**)&aol, g_aol);

    cudaFuncSetAttribute(k_gemm_bt, cudaFuncAttributeMaxDynamicSharedMemorySize, SMEM_TB_BYTES);
    cudaFuncSetAttribute(k_flash,   cudaFuncAttributeMaxDynamicSharedMemorySize, FA_SMEM_BYTES);

    const int M = B_ * L_;
    dim3 blk(256);

    auto launch_split = [&](const float* src, bf16* hi, bf16* lo, int n) {
        int n4 = n / 4;
        k_split<<<(n4 + 255) / 256, 256>>>((const float4*)src, (ushort4*)hi, (ushort4*)lo, n4);
    };

    // splits of inputs/weights
    launch_split(x,  xh,  xl,  M * D_);
    launch_split(Wq, wqh, wql, D_ * D_);
    launch_split(Wk, wkh, wkl, KVH_ * HD_ * D_);
    launch_split(Wv, wvh, wvl, KVH_ * HD_ * D_);
    launch_split(Wo, woh, wol, D_ * D_);

    // projections
    k_gemm_bt<<<dim3(D_/BN,         M/BM), blk, SMEM_TB_BYTES>>>(xh, xl, D_, wqh, wql, D_, q, D_,       D_);
    k_gemm_bt<<<dim3((KVH_*HD_)/BN, M/BM), blk, SMEM_TB_BYTES>>>(xh, xl, D_, wkh, wkl, D_, k, KVH_*HD_, D_);
    k_gemm_bt<<<dim3((KVH_*HD_)/BN, M/BM), blk, SMEM_TB_BYTES>>>(xh, xl, D_, wvh, wvl, D_, v, KVH_*HD_, D_);

    // rmsnorm + rope -> bf16 planes
    rms_rope_split_kernel<<<(B_ * L_ * H_)   / 8, 256>>>(q, qg, qhp, qlp, H_);
    rms_rope_split_kernel<<<(B_ * L_ * KVH_) / 8, 256>>>(k, kg, khp, klp, KVH_);

    // V transpose + split
    k_vtrans<<<dim3(L_/32, HD_/32, B_*KVH_), 256>>>(v, vth, vtl);

    // fused flash attention -> ao bf16 planes
    k_flash<<<dim3(L_/128, H_, B_), 256, FA_SMEM_BYTES>>>(qhp, qlp, khp, klp,
                                                          vth, vtl, mask, aoh, aol);

    // output projection
    k_gemm_bt<<<dim3(D_/BN, M/BM), blk, SMEM_TB_BYTES>>>(aoh, aol, D_, woh, wol, D_, out, D_, D_);
}

// round 5
// speedup vs baseline: 5.5697x; 1.3827x over previous
#include <cuda_runtime.h>
#include <cuda_fp16.h>
#include <math.h>
#include <math_constants.h>
#include <stdint.h>

#define B_    2
#define L_    2048
#define D_    2048
#define H_    16
#define KVH_  4
#define HD_   128
#define EPS_  1e-6f

typedef __half h16;

// ---------------------------------------------------------------------------
// Static scratch
// ---------------------------------------------------------------------------
__device__ float g_q [B_*L_*D_];
__device__ float g_k [B_*L_*KVH_*HD_];
__device__ float g_v [B_*L_*KVH_*HD_];

__device__ h16 g_xh [B_*L_*D_],      g_xl [B_*L_*D_];
__device__ h16 g_wq [D_*D_];
__device__ h16 g_wk [KVH_*HD_*D_];
__device__ h16 g_wv [KVH_*HD_*D_];
__device__ h16 g_wo [D_*D_];
__device__ h16 g_qh [B_*L_*D_],      g_ql [B_*L_*D_];
__device__ h16 g_kh [B_*L_*KVH_*HD_];
__device__ h16 g_vt [B_*KVH_*HD_*L_];                 // V transposed [b][kvh][d][L]
__device__ h16 g_aoh[B_*L_*D_],      g_aol[B_*L_*D_];

// ---------------------------------------------------------------------------
// PTX helpers
// ---------------------------------------------------------------------------
__device__ __forceinline__ void mma_f16(float* c, const uint32_t* a, const uint32_t* b) {
    asm volatile(
        "mma.sync.aligned.m16n8k16.row.col.f32.f16.f16.f32 "
        "{%0,%1,%2,%3}, {%4,%5,%6,%7}, {%8,%9}, {%0,%1,%2,%3};\n"
        : "+f"(c[0]), "+f"(c[1]), "+f"(c[2]), "+f"(c[3])
        : "r"(a[0]), "r"(a[1]), "r"(a[2]), "r"(a[3]), "r"(b[0]), "r"(b[1]));
}

__device__ __forceinline__ void cp16(const h16* dst_s, const h16* src_g) {
    uint32_t d = (uint32_t)__cvta_generic_to_shared(dst_s);
    asm volatile("cp.async.cg.shared.global [%0], [%1], 16;\n"
                 :: "r"(d), "l"(src_g) : "memory");
}
__device__ __forceinline__ void cp_commit() {
    asm volatile("cp.async.commit_group;\n" ::: "memory");
}
template<int N>
__device__ __forceinline__ void cp_wait() {
    asm volatile("cp.async.wait_group %0;\n" :: "n"(N) : "memory");
}

__device__ __forceinline__ uint32_t pack2(h16 a, h16 b) {
    uint32_t x = *reinterpret_cast<unsigned short*>(&a);
    uint32_t y = *reinterpret_cast<unsigned short*>(&b);
    return x | (y << 16);
}

__device__ __forceinline__ void split1(float x, unsigned short& h, unsigned short& l) {
    h16 hh = __float2half_rn(x);
    h16 ll = __float2half_rn(x - __half2float(hh));
    h = *reinterpret_cast<unsigned short*>(&hh);
    l = *reinterpret_cast<unsigned short*>(&ll);
}

// ---------------------------------------------------------------------------
// Projection GEMM: C[M,N] fp32 = (Ah+Al)[M,K] * Bh[N,K]^T, fp16 2-product
// 128x128 tile, BK=32, 256 threads (8 warps = 2x4), double-buffered cp.async.
// ---------------------------------------------------------------------------
#define BM 128
#define BN 128
#define BK 32
#define APAD 40

#define SM_A_HALVES (2*2*BM*APAD)        // 2 buf x 2 planes
#define SM_B_HALVES (2*BN*APAD)          // 2 buf x 1 plane
#define SMEM_TB_BYTES ((SM_A_HALVES + SM_B_HALVES)*2)   // 61440

__global__ __launch_bounds__(256, 1)
void k_gemm_bt(const h16* __restrict__ Ah, const h16* __restrict__ Al, int lda,
               const h16* __restrict__ Bh, int ldb,
               float* __restrict__ C, int ldc, int K)
{
    extern __shared__ h16 sh[];
    h16* sA = sh;
    h16* sB = sh + SM_A_HALVES;

    const int tid = threadIdx.x;
    const int m0 = blockIdx.y * BM;
    const int n0 = blockIdx.x * BN;

    const h16* Ap[2] = { Ah + (size_t)m0 * lda, Al + (size_t)m0 * lda };
    const h16* Bp    =   Bh + (size_t)n0 * ldb;

    const int lane = tid & 31;
    const int g    = lane >> 2;
    const int t    = lane & 3;
    const int warp = tid >> 5;
    const int wm   = warp >> 2;
    const int wn   = warp & 3;

    float acc[4][4][4];
#pragma unroll
    for (int i = 0; i < 4; i++)
#pragma unroll
        for (int j = 0; j < 4; j++)
#pragma unroll
            for (int c = 0; c < 4; c++) acc[i][j][c] = 0.f;

    auto load_stage = [&](int s, int k0) {
#pragma unroll
        for (int p = 0; p < 2; p++) {
#pragma unroll
            for (int i = 0; i < 2; i++) {
                int c   = tid + i * 256;
                int row = c >> 2, kc = c & 3;
                cp16(sA + (size_t)(s*2+p)*BM*APAD + row*APAD + kc*8,
                     Ap[p] + (size_t)row * lda + k0 + kc*8);
            }
        }
#pragma unroll
        for (int i = 0; i < 2; i++) {
            int c   = tid + i * 256;
            int row = c >> 2, kc = c & 3;
            cp16(sB + (size_t)s*BN*APAD + row*APAD + kc*8,
                 Bp + (size_t)row * ldb + k0 + kc*8);
        }
    };

    const int nk = K / BK;
    load_stage(0, 0);
    cp_commit();

    for (int ks = 0; ks < nk; ks++) {
        const int buf = ks & 1;
        if (ks + 1 < nk) {
            load_stage(buf ^ 1, (ks + 1) * BK);
            cp_commit();
            cp_wait<1>();
        } else {
            cp_wait<0>();
        }
        __syncthreads();

        const h16* sAh = sA + (size_t)(buf*2+0)*BM*APAD;
        const h16* sAl = sA + (size_t)(buf*2+1)*BM*APAD;
        const h16* sBh = sB + (size_t)buf*BN*APAD;

#pragma unroll
        for (int kk = 0; kk < 2; kk++) {
            const int ko = kk * 16;

            uint32_t ah[4][4], alr[4][4];
#pragma unroll
            for (int mt = 0; mt < 4; mt++) {
                const int r = wm*64 + mt*16 + g;
                const h16* p0 = sAh + r*APAD + ko + 2*t;
                ah[mt][0] = *(const uint32_t*)(p0);
                ah[mt][1] = *(const uint32_t*)(p0 + 8*APAD);
                ah[mt][2] = *(const uint32_t*)(p0 + 8);
                ah[mt][3] = *(const uint32_t*)(p0 + 8*APAD + 8);
                const h16* p1 = sAl + r*APAD + ko + 2*t;
                alr[mt][0] = *(const uint32_t*)(p1);
                alr[mt][1] = *(const uint32_t*)(p1 + 8*APAD);
                alr[mt][2] = *(const uint32_t*)(p1 + 8);
                alr[mt][3] = *(const uint32_t*)(p1 + 8*APAD + 8);
            }

            uint32_t bh[4][2];
#pragma unroll
            for (int nt = 0; nt < 4; nt++) {
                const int n = wn*32 + nt*8 + g;
                const h16* p0 = sBh + n*APAD + ko + 2*t;
                bh[nt][0] = *(const uint32_t*)(p0);
                bh[nt][1] = *(const uint32_t*)(p0 + 8);
            }

#pragma unroll
            for (int mt = 0; mt < 4; mt++)
#pragma unroll
                for (int nt = 0; nt < 4; nt++) {
                    mma_f16(acc[mt][nt], ah[mt],  bh[nt]);
                    mma_f16(acc[mt][nt], alr[mt], bh[nt]);
                }
        }
        __syncthreads();
    }

#pragma unroll
    for (int mt = 0; mt < 4; mt++) {
        const int r = m0 + wm*64 + mt*16 + g;
#pragma unroll
        for (int nt = 0; nt < 4; nt++) {
            const int c = n0 + wn*32 + nt*8 + 2*t;
            *reinterpret_cast<float2*>(&C[(size_t)r     * ldc + c]) =
                make_float2(acc[mt][nt][0], acc[mt][nt][1]);
            *reinterpret_cast<float2*>(&C[(size_t)(r+8) * ldc + c]) =
                make_float2(acc[mt][nt][2], acc[mt][nt][3]);
        }
    }
}

// ---------------------------------------------------------------------------
// fp32 -> (hi, lo) fp16 split  /  fp32 -> fp16 convert
// ---------------------------------------------------------------------------
__global__ void k_split(const float4* __restrict__ X,
                        ushort4* __restrict__ Hi, ushort4* __restrict__ Lo, int n4)
{
    int i = blockIdx.x * blockDim.x + threadIdx.x;
    if (i >= n4) return;
    float4 v = X[i];
    ushort4 hv, lv;
    split1(v.x, hv.x, lv.x);
    split1(v.y, hv.y, lv.y);
    split1(v.z, hv.z, lv.z);
    split1(v.w, hv.w, lv.w);
    Hi[i] = hv;
    Lo[i] = lv;
}

__global__ void k_cvt(const float4* __restrict__ X, ushort4* __restrict__ Hi, int n4)
{
    int i = blockIdx.x * blockDim.x + threadIdx.x;
    if (i >= n4) return;
    float4 v = X[i];
    h16 a = __float2half_rn(v.x), b = __float2half_rn(v.y);
    h16 c = __float2half_rn(v.z), d = __float2half_rn(v.w);
    ushort4 hv;
    hv.x = *reinterpret_cast<unsigned short*>(&a);
    hv.y = *reinterpret_cast<unsigned short*>(&b);
    hv.z = *reinterpret_cast<unsigned short*>(&c);
    hv.w = *reinterpret_cast<unsigned short*>(&d);
    Hi[i] = hv;
}

// ---------------------------------------------------------------------------
// RMSNorm + RoPE, fp32 in -> fp16 hi (+ optional lo) planes. One warp/(b,l,h).
// ---------------------------------------------------------------------------
__global__ void rms_rope_split_kernel(const float* __restrict__ X,
                                      const float* __restrict__ gamma,
                                      h16* __restrict__ Xh, h16* __restrict__ Xl,
                                      int heads) {
    const int warp = (blockIdx.x * blockDim.x + threadIdx.x) >> 5;
    const int lane = threadIdx.x & 31;
    const int h = warp % heads;
    const int l = (warp / heads) % L_;
    const int b = warp / (heads * L_);

    const size_t base = ((size_t)(b * L_ + l) * heads + h) * HD_;
    const float* vec = X + base;

    const int p0 = lane, p1 = lane + 32;
    float x0a = vec[2*p0],   x1a = vec[2*p0+1];
    float x0b = vec[2*p1],   x1b = vec[2*p1+1];

    float ss = x0a*x0a + x1a*x1a + x0b*x0b + x1b*x1b;
#pragma unroll
    for (int off = 16; off; off >>= 1)
        ss += __shfl_xor_sync(0xffffffffu, ss, off);

    const float inv = rsqrtf(ss * (1.0f / HD_) + EPS_);
    const float LOG2_THETA = 13.287712379549449f;
    const float fl = (float)l;

    unsigned short hh, ll;
    {
        float g0 = gamma[2*p0], g1 = gamma[2*p0+1];
        float re = x0a * inv * g0, im = x1a * inv * g1;
        float fr = fl * exp2f(-(2.0f * p0 / (float)HD_) * LOG2_THETA);
        float s, c; sincosf(fr, &s, &c);
        float o0 = re * c - im * s, o1 = re * s + im * c;
        split1(o0, hh, ll);
        ((unsigned short*)Xh)[base + 2*p0] = hh;
        if (Xl) ((unsigned short*)Xl)[base + 2*p0] = ll;
        split1(o1, hh, ll);
        ((unsigned short*)Xh)[base + 2*p0+1] = hh;
        if (Xl) ((unsigned short*)Xl)[base + 2*p0+1] = ll;
    }
    {
        float g0 = gamma[2*p1], g1 = gamma[2*p1+1];
        float re = x0b * inv * g0, im = x1b * inv * g1;
        float fr = fl * exp2f(-(2.0f * p1 / (float)HD_) * LOG2_THETA);
        float s, c; sincosf(fr, &s, &c);
        float o0 = re * c - im * s, o1 = re * s + im * c;
        split1(o0, hh, ll);
        ((unsigned short*)Xh)[base + 2*p1] = hh;
        if (Xl) ((unsigned short*)Xl)[base + 2*p1] = ll;
        split1(o1, hh, ll);
        ((unsigned short*)Xh)[base + 2*p1+1] = hh;
        if (Xl) ((unsigned short*)Xl)[base + 2*p1+1] = ll;
    }
}

// ---------------------------------------------------------------------------
// V transpose: v fp32 [b][l][kvh][d] -> vt fp16 [b][kvh][d][L]
// ---------------------------------------------------------------------------
__global__ void k_vtrans(const float* __restrict__ V, h16* __restrict__ Vt)
{
    __shared__ float tile[32][33];
    const int tx = threadIdx.x & 31;
    const int ty = threadIdx.x >> 5;
    const int l0 = blockIdx.x * 32;
    const int d0 = blockIdx.y * 32;
    const int z  = blockIdx.z;
    const int b  = z >> 2, kvh = z & 3;

#pragma unroll
    for (int i = 0; i < 4; i++) {
        int l = l0 + ty + i*8;
        tile[ty + i*8][tx] =
            V[((size_t)(b*L_ + l) * KVH_ + kvh) * HD_ + d0 + tx];
    }
    __syncthreads();
#pragma unroll
    for (int i = 0; i < 4; i++) {
        int d = d0 + ty + i*8;
        h16 val = __float2half_rn(tile[tx][ty + i*8]);
        size_t idx = ((size_t)(b*KVH_ + kvh) * HD_ + d) * L_ + l0 + tx;
        Vt[idx] = val;
    }
}

// ---------------------------------------------------------------------------
// Fused flash attention, fp16 2-product MMA, online softmax on fragments.
// Block: (q-tile 128, head, batch). 256 threads = 8 warps, 16 q-rows each.
// Q: 2 planes; K, V: single plane, double-buffered.
// ---------------------------------------------------------------------------
#define QPAD 136
#define VPAD 72

#define QPL  (128*QPAD)           // 17408
#define KPL  (64*QPAD)            // 8704
#define VPL  (128*VPAD)           // 9216
#define QS_OFF 0
#define KS_OFF (2*QPL)            // 34816
#define VS_OFF (KS_OFF + 2*KPL)   // 52224
#define MS_OFF_H (VS_OFF + 2*VPL) // 70656 halves
#define FA_SMEM_BYTES (MS_OFF_H*2 + 2*64*4)   // 141824

__global__ __launch_bounds__(256, 1)
void k_flash(const h16* __restrict__ qh, const h16* __restrict__ ql,
             const h16* __restrict__ kh,
             const h16* __restrict__ vt,
             const int* __restrict__ mask,
             h16* __restrict__ aoh, h16* __restrict__ aol)
{
    extern __shared__ h16 sm[];
    h16*   Qs = sm + QS_OFF;
    h16*   Ks = sm + KS_OFF;
    h16*   Vs = sm + VS_OFF;
    float* Ms = (float*)(sm + MS_OFF_H);

    const int tid  = threadIdx.x;
    const int lane = tid & 31;
    const int g    = lane >> 2;
    const int t    = lane & 3;
    const int w    = tid >> 5;

    const int qt = blockIdx.x, h = blockIdx.y, b = blockIdx.z;
    const int kvh = h >> 2;
    const int q0  = qt * 128;

    const h16* Qg[2] = { qh + ((size_t)(b*L_ + q0)) * D_ + h * HD_,
                         ql + ((size_t)(b*L_ + q0)) * D_ + h * HD_ };
    const h16* Kg = kh + ((size_t)(b*L_)) * (KVH_*HD_) + kvh * HD_;
    const h16* Vg = vt + ((size_t)(b*KVH_ + kvh)) * HD_ * L_;

    // Q load (once): 2 planes x 128 rows x 16 chunks
#pragma unroll
    for (int p = 0; p < 2; p++)
#pragma unroll
        for (int i = 0; i < 8; i++) {
            int c = tid + i * 256;
            int row = c >> 4, ch = c & 15;
            cp16(Qs + p*QPL + row*QPAD + ch*8, Qg[p] + (size_t)row * D_ + ch*8);
        }

    auto load_stage = [&](int s, int kt) {
        const int j0 = kt * 64;
#pragma unroll
        for (int i = 0; i < 4; i++) {          // K: 64 rows x 16 chunks
            int c = tid + i * 256;
            int row = c >> 4, ch = c & 15;
            cp16(Ks + s*KPL + row*QPAD + ch*8,
                 Kg + (size_t)(j0 + row) * (KVH_*HD_) + ch*8);
        }
#pragma unroll
        for (int i = 0; i < 4; i++) {          // V: 128 rows x 8 chunks
            int c = tid + i * 256;
            int row = c >> 3, ch = c & 7;
            cp16(Vs + s*VPL + row*VPAD + ch*8,
                 Vg + (size_t)row * L_ + j0 + ch*8);
        }
        if (tid < 64)
            Ms[s*64 + tid] = mask[b*L_ + j0 + tid] ? 0.f : -1e30f;
    };

    load_stage(0, 0);
    cp_commit();

    float o[16][4];
#pragma unroll
    for (int i = 0; i < 16; i++)
#pragma unroll
        for (int c = 0; c < 4; c++) o[i][c] = 0.f;

    float mprev0 = -1e30f, mprev1 = -1e30f;
    float lsum0 = 0.f, lsum1 = 0.f;
    const float sc = 0.08838834764831845f;

    const int NT_ = L_ / 64;
    for (int kt = 0; kt < NT_; kt++) {
        const int buf = kt & 1;
        if (kt + 1 < NT_) {
            load_stage(buf ^ 1, kt + 1);
            cp_commit();
            cp_wait<1>();
        } else {
            cp_wait<0>();
        }
        __syncthreads();

        // S = Q K^T : per warp m16 x n64 x k128, 2 products
        float s[8][4];
#pragma unroll
        for (int nt = 0; nt < 8; nt++)
#pragma unroll
            for (int c = 0; c < 4; c++) s[nt][c] = 0.f;

        const h16* qbh = Qs + (w*16 + g)*QPAD + 2*t;
        const h16* qbl = qbh + QPL;
        const h16* kb  = Ks + buf*KPL + g*QPAD + 2*t;

#pragma unroll
        for (int kk = 0; kk < 8; kk++) {
            const int ko = kk * 16;
            uint32_t ah[4], al[4];
            ah[0] = *(const uint32_t*)(qbh + ko);
            ah[1] = *(const uint32_t*)(qbh + ko + 8*QPAD);
            ah[2] = *(const uint32_t*)(qbh + ko + 8);
            ah[3] = *(const uint32_t*)(qbh + ko + 8*QPAD + 8);
            al[0] = *(const uint32_t*)(qbl + ko);
            al[1] = *(const uint32_t*)(qbl + ko + 8*QPAD);
            al[2] = *(const uint32_t*)(qbl + ko + 8);
            al[3] = *(const uint32_t*)(qbl + ko + 8*QPAD + 8);
#pragma unroll
            for (int nt = 0; nt < 8; nt++) {
                uint32_t bh[2];
                const h16* pk = kb + nt*8*QPAD + ko;
                bh[0] = *(const uint32_t*)(pk);
                bh[1] = *(const uint32_t*)(pk + 8);
                mma_f16(s[nt], ah, bh);
                mma_f16(s[nt], al, bh);
            }
        }

        // online softmax on fragments
        const float* msf = Ms + buf*64;
        float m0 = -1e30f, m1 = -1e30f;
#pragma unroll
        for (int nt = 0; nt < 8; nt++) {
            float b0 = msf[8*nt + 2*t], b1 = msf[8*nt + 2*t + 1];
            s[nt][0] = s[nt][0]*sc + b0;
            s[nt][1] = s[nt][1]*sc + b1;
            s[nt][2] = s[nt][2]*sc + b0;
            s[nt][3] = s[nt][3]*sc + b1;
            m0 = fmaxf(m0, fmaxf(s[nt][0], s[nt][1]));
            m1 = fmaxf(m1, fmaxf(s[nt][2], s[nt][3]));
        }
        m0 = fmaxf(m0, __shfl_xor_sync(0xffffffffu, m0, 1));
        m0 = fmaxf(m0, __shfl_xor_sync(0xffffffffu, m0, 2));
        m1 = fmaxf(m1, __shfl_xor_sync(0xffffffffu, m1, 1));
        m1 = fmaxf(m1, __shfl_xor_sync(0xffffffffu, m1, 2));

        const float mn0 = fmaxf(mprev0, m0);
        const float mn1 = fmaxf(mprev1, m1);
        const float alpha0 = __expf(mprev0 - mn0);
        const float alpha1 = __expf(mprev1 - mn1);
        mprev0 = mn0; mprev1 = mn1;

        float sum0 = 0.f, sum1 = 0.f;
#pragma unroll
        for (int nt = 0; nt < 8; nt++) {
            s[nt][0] = __expf(s[nt][0] - mn0);
            s[nt][1] = __expf(s[nt][1] - mn0);
            s[nt][2] = __expf(s[nt][2] - mn1);
            s[nt][3] = __expf(s[nt][3] - mn1);
            sum0 += s[nt][0] + s[nt][1];
            sum1 += s[nt][2] + s[nt][3];
        }
        sum0 += __shfl_xor_sync(0xffffffffu, sum0, 1);
        sum0 += __shfl_xor_sync(0xffffffffu, sum0, 2);
        sum1 += __shfl_xor_sync(0xffffffffu, sum1, 1);
        sum1 += __shfl_xor_sync(0xffffffffu, sum1, 2);
        lsum0 = lsum0 * alpha0 + sum0;
        lsum1 = lsum1 * alpha1 + sum1;

#pragma unroll
        for (int nt = 0; nt < 16; nt++) {
            o[nt][0] *= alpha0; o[nt][1] *= alpha0;
            o[nt][2] *= alpha1; o[nt][3] *= alpha1;
        }

        // P fragments (register-local split to fp16 hi/lo)
        uint32_t pah[4][4], pal[4][4];
#pragma unroll
        for (int kk = 0; kk < 4; kk++) {
            const int n0t = 2*kk, n1t = 2*kk + 1;
            float p00 = s[n0t][0], p01 = s[n0t][1], p02 = s[n0t][2], p03 = s[n0t][3];
            float p10 = s[n1t][0], p11 = s[n1t][1], p12 = s[n1t][2], p13 = s[n1t][3];
            h16 h00 = __float2half_rn(p00), h01 = __float2half_rn(p01);
            h16 h02 = __float2half_rn(p02), h03 = __float2half_rn(p03);
            h16 h10 = __float2half_rn(p10), h11 = __float2half_rn(p11);
            h16 h12 = __float2half_rn(p12), h13 = __float2half_rn(p13);
            pah[kk][0] = pack2(h00, h01);
            pah[kk][1] = pack2(h02, h03);
            pah[kk][2] = pack2(h10, h11);
            pah[kk][3] = pack2(h12, h13);
            pal[kk][0] = pack2(__float2half_rn(p00 - __half2float(h00)),
                               __float2half_rn(p01 - __half2float(h01)));
            pal[kk][1] = pack2(__float2half_rn(p02 - __half2float(h02)),
                               __float2half_rn(p03 - __half2float(h03)));
            pal[kk][2] = pack2(__float2half_rn(p10 - __half2float(h10)),
                               __float2half_rn(p11 - __half2float(h11)));
            pal[kk][3] = pack2(__float2half_rn(p12 - __half2float(h12)),
                               __float2half_rn(p13 - __half2float(h13)));
        }

        // O += P V : per warp m16 x n128 x k64, 2 products
        const h16* vb = Vs + buf*VPL + g*VPAD + 2*t;
#pragma unroll
        for (int kk = 0; kk < 4; kk++) {
            const int ko = kk * 16;
#pragma unroll
            for (int nt = 0; nt < 16; nt++) {
                uint32_t bh[2];
                const h16* pv = vb + nt*8*VPAD + ko;
                bh[0] = *(const uint32_t*)(pv);
                bh[1] = *(const uint32_t*)(pv + 8);
                mma_f16(o[nt], pah[kk], bh);
                mma_f16(o[nt], pal[kk], bh);
            }
        }
        __syncthreads();
    }

    // epilogue: normalize, split, store fp16 hi/lo
    const float inv0 = lsum0 > 0.f ? 1.f / lsum0 : 0.f;
    const float inv1 = lsum1 > 0.f ? 1.f / lsum1 : 0.f;
    const int row0 = q0 + w*16 + g;
    const size_t base0 = (size_t)(b*L_ + row0) * D_ + h * HD_;
    const size_t base1 = base0 + 8 * (size_t)D_;

#pragma unroll
    for (int nt = 0; nt < 16; nt++) {
        const int col = nt*8 + 2*t;
        float v0 = o[nt][0] * inv0, v1 = o[nt][1] * inv0;
        float v2 = o[nt][2] * inv1, v3 = o[nt][3] * inv1;
        h16 h0 = __float2half_rn(v0), h1 = __float2half_rn(v1);
        h16 h2 = __float2half_rn(v2), h3 = __float2half_rn(v3);
        *(uint32_t*)(aoh + base0 + col) = pack2(h0, h1);
        *(uint32_t*)(aoh + base1 + col) = pack2(h2, h3);
        *(uint32_t*)(aol + base0 + col) =
            pack2(__float2half_rn(v0 - __half2float(h0)),
                  __float2half_rn(v1 - __half2float(h1)));
        *(uint32_t*)(aol + base1 + col) =
            pack2(__float2half_rn(v2 - __half2float(h2)),
                  __float2half_rn(v3 - __half2float(h3)));
    }
}

// ---------------------------------------------------------------------------
// Launch
// ---------------------------------------------------------------------------
extern "C" void kernel_launch(void* const* d_in, const int* in_sizes, int n_in,
                              void* d_out, int out_size) {
    const float* x    = (const float*)d_in[0];
    const int*   mask = (const int*)  d_in[1];
    const float* Wq   = (const float*)d_in[2];
    const float* Wk   = (const float*)d_in[3];
    const float* Wv   = (const float*)d_in[4];
    const float* Wo   = (const float*)d_in[5];
    const float* qg   = (const float*)d_in[6];
    const float* kg   = (const float*)d_in[7];
    float* out = (float*)d_out;

    float *q, *k, *v;
    h16 *xh, *xl, *wq, *wk, *wv, *wo;
    h16 *qhp, *qlp, *khp, *vtp, *aoh, *aol;
    cudaGetSymbolAddress((void**)&q,   g_q);
    cudaGetSymbolAddress((void**)&k,   g_k);
    cudaGetSymbolAddress((void**)&v,   g_v);
    cudaGetSymbolAddress((void**)&xh,  g_xh);  cudaGetSymbolAddress((void**)&xl,  g_xl);
    cudaGetSymbolAddress((void**)&wq,  g_wq);
    cudaGetSymbolAddress((void**)&wk,  g_wk);
    cudaGetSymbolAddress((void**)&wv,  g_wv);
    cudaGetSymbolAddress((void**)&wo,  g_wo);
    cudaGetSymbolAddress((void**)&qhp, g_qh);  cudaGetSymbolAddress((void**)&qlp, g_ql);
    cudaGetSymbolAddress((void**)&khp, g_kh);
    cudaGetSymbolAddress((void**)&vtp, g_vt);
    cudaGetSymbolAddress((void**)&aoh, g_aoh); cudaGetSymbolAddress((void**)&aol, g_aol);

    cudaFuncSetAttribute(k_gemm_bt, cudaFuncAttributeMaxDynamicSharedMemorySize, SMEM_TB_BYTES);
    cudaFuncSetAttribute(k_flash,   cudaFuncAttributeMaxDynamicSharedMemorySize, FA_SMEM_BYTES);

    const int M = B_ * L_;
    dim3 blk(256);

    auto launch_split = [&](const float* src, h16* hi, h16* lo, int n) {
        int n4 = n / 4;
        k_split<<<(n4 + 255) / 256, 256>>>((const float4*)src, (ushort4*)hi, (ushort4*)lo, n4);
    };
    auto launch_cvt = [&](const float* src, h16* hi, int n) {
        int n4 = n / 4;
        k_cvt<<<(n4 + 255) / 256, 256>>>((const float4*)src, (ushort4*)hi, n4);
    };

    // input split (2-term), weights single fp16
    launch_split(x, xh, xl, M * D_);
    launch_cvt(Wq, wq, D_ * D_);
    launch_cvt(Wk, wk, KVH_ * HD_ * D_);
    launch_cvt(Wv, wv, KVH_ * HD_ * D_);
    launch_cvt(Wo, wo, D_ * D_);

    // projections (fp16 2-product tensor-core GEMM)
    k_gemm_bt<<<dim3(D_/BN,         M/BM), blk, SMEM_TB_BYTES>>>(xh, xl, D_, wq, D_, q, D_,       D_);
    k_gemm_bt<<<dim3((KVH_*HD_)/BN, M/BM), blk, SMEM_TB_BYTES>>>(xh, xl, D_, wk, D_, k, KVH_*HD_, D_);
    k_gemm_bt<<<dim3((KVH_*HD_)/BN, M/BM), blk, SMEM_TB_BYTES>>>(xh, xl, D_, wv, D_, v, KVH_*HD_, D_);

    // rmsnorm + rope -> fp16 planes (q 2-term, k 1-term)
    rms_rope_split_kernel<<<(B_ * L_ * H_)   / 8, 256>>>(q, qg, qhp, qlp, H_);
    rms_rope_split_kernel<<<(B_ * L_ * KVH_) / 8, 256>>>(k, kg, khp, (h16*)nullptr, KVH_);

    // V transpose (single fp16)
    k_vtrans<<<dim3(L_/32, HD_/32, B_*KVH_), 256>>>(v, vtp);

    // fused flash attention -> ao fp16 hi/lo planes
    k_flash<<<dim3(L_/128, H_, B_), 256, FA_SMEM_BYTES>>>(qhp, qlp, khp, vtp,
                                                          mask, aoh, aol);

    // output projection
    k_gemm_bt<<<dim3(D_/BN, M/BM), blk, SMEM_TB_BYTES>>>(aoh, aol, D_, wo, D_, out, D_, D_);
}